// round 1
// baseline (speedup 1.0000x reference)
#include <cuda_runtime.h>
#include <math.h>
#include <float.h>

// ---------------- problem constants ----------------
#define BB   2
#define T0C  1024
#define TOTC 2048
#define DC   2048
#define NC   16
#define KC   8
#define HC   128
#define FC   8192
#define NHC  2048   // N*H
#define KHC  1024   // K*H
#define GC   2      // N/K

// ---------------- scratch (device globals; no runtime alloc) ----------------
__device__ float g_pre [BB*TOTC*DC];
__device__ float g_q   [(size_t)BB*TOTC*NHC];
__device__ float g_k   [(size_t)BB*TOTC*KHC];
__device__ float g_v   [(size_t)BB*TOTC*KHC];
__device__ float g_enc [(size_t)BB*TOTC*NHC];
__device__ float g_res [(size_t)BB*TOTC*DC];
__device__ float g_hid [(size_t)BB*TOTC*DC];
__device__ float g_gate[(size_t)BB*TOTC*FC];
__device__ float g_up  [(size_t)BB*TOTC*FC];

// ---------------- rmsnorm ----------------
// srcmode 0: src is (B,T0,D) stream tensor, row = b*T0+t
// srcmode 1: src is (B,TOT,D) concat tensor at concat row
__global__ void rmsnorm_kernel(const float* __restrict__ src, float* __restrict__ dst,
                               const float* __restrict__ scale, int istream, int srcmode)
{
    int row = blockIdx.x;               // 0 .. B*T0-1
    int b = row / T0C, t = row % T0C;
    size_t crow = (size_t)b*TOTC + (size_t)istream*T0C + t;
    const float* s = src + (srcmode ? crow : (size_t)row) * DC;
    float* o = dst + crow * DC;

    __shared__ float red[256];
    float ss = 0.f;
    for (int d = threadIdx.x; d < DC; d += 256) { float v = s[d]; ss += v*v; }
    red[threadIdx.x] = ss;
    __syncthreads();
    for (int st = 128; st > 0; st >>= 1) {
        if (threadIdx.x < st) red[threadIdx.x] += red[threadIdx.x + st];
        __syncthreads();
    }
    float inv = rsqrtf(red[0] * (1.0f/DC) + 1e-6f);
    for (int d = threadIdx.x; d < DC; d += 256)
        o[d] = s[d] * inv * (1.0f + scale[d]);
}

// ---------------- rope (in-place on q and k, q also scaled by H^-0.5) ----------------
__global__ void rope_kernel(float* __restrict__ q, float* __restrict__ k,
                            const int* __restrict__ positions)
{
    int row = blockIdx.x;                       // b*TOT + t
    float pos = (float)positions[row];
    const float QSCALE = 0.08838834764831845f;  // 128^-0.5
    for (int w = threadIdx.x; w < (NC + KC) * 64; w += blockDim.x) {
        int head = w >> 6;
        int j = w & 63;
        float ts = powf(10000.0f, (float)j * (1.0f/64.0f));
        float rad = pos / ts;
        float sn, cs;
        sincosf(rad, &sn, &cs);
        if (head < NC) {
            float* p = q + ((size_t)row * NC + head) * HC;
            float x1 = p[j], x2 = p[j + 64];
            p[j]      = (x1*cs - x2*sn) * QSCALE;
            p[j + 64] = (x2*cs + x1*sn) * QSCALE;
        } else {
            float* p = k + ((size_t)row * KC + (head - NC)) * HC;
            float x1 = p[j], x2 = p[j + 64];
            p[j]      = x1*cs - x2*sn;
            p[j + 64] = x2*cs + x1*sn;
        }
    }
}

// ---------------- GEMM: C = A @ W^T (+epilogue) ----------------
// A: (M=1024 rows per z-slice, Kd) row-major, W: (Nout, Kd) row-major.
// z = i*2 + b  (i = stream, b = batch). Scratch tensors are concat-time layout.
// epi: 0 none, 1 gelu(tanh), 2 add-residual
// afuse: A_eff = A * aux (elementwise) during tile load
// resmode: 0 residual from per-stream ptr (R0/R1, + b*T0*Nout), 1 from concat ptr R0 (+ arow0*Nout)
// outmode: 0 concat-time C offset, 1 stream-major output (out0 | out1)
__device__ __forceinline__ float gelu_tanh(float x) {
    float x3 = x * x * x;
    return 0.5f * x * (1.0f + tanhf(0.7978845608028654f * (x + 0.044715f * x3)));
}

#define GBM 128
#define GBN 128
#define GBK 16

__global__ __launch_bounds__(256)
void gemm_kernel(const float* __restrict__ A_,
                 const float* __restrict__ W0, const float* __restrict__ W1,
                 float* __restrict__ C_,
                 int Kd, int Nout,
                 int epi, int afuse,
                 const float* __restrict__ aux_,
                 const float* __restrict__ R0, const float* __restrict__ R1,
                 int resmode, int outmode)
{
    int z = blockIdx.z;
    int i = z >> 1, b = z & 1;
    size_t arow0 = (size_t)b * TOTC + (size_t)i * T0C;

    const float* A   = A_ + arow0 * Kd;
    const float* aux = afuse ? (aux_ + arow0 * Kd) : A_;
    const float* W   = i ? W1 : W0;
    float* C = (outmode == 0) ? (C_ + arow0 * (size_t)Nout)
                              : (C_ + ((size_t)i * BB * T0C + (size_t)b * T0C) * Nout);
    const float* R = 0;
    if (epi == 2) {
        if (resmode == 0) R = (i ? R1 : R0) + (size_t)b * T0C * Nout;
        else              R = R0 + arow0 * (size_t)Nout;
    }

    int m0 = blockIdx.y * GBM;
    int n0 = blockIdx.x * GBN;

    __shared__ float As[GBK][GBM + 4];
    __shared__ float Ws[GBK][GBN + 4];

    int tid = threadIdx.x;
    int tx = tid & 15, ty = tid >> 4;

    float acc[8][8];
    #pragma unroll
    for (int r = 0; r < 8; ++r)
        #pragma unroll
        for (int c = 0; c < 8; ++c) acc[r][c] = 0.f;

    for (int k0 = 0; k0 < Kd; k0 += GBK) {
        // load A tile (and fuse aux), W tile; 2 float4 each per thread
        #pragma unroll
        for (int it = 0; it < 2; ++it) {
            int idx = tid + 256 * it;
            int row = idx >> 2, c4 = idx & 3;
            float4 av = *(const float4*)(A + (size_t)(m0 + row) * Kd + k0 + c4 * 4);
            if (afuse) {
                float4 uv = *(const float4*)(aux + (size_t)(m0 + row) * Kd + k0 + c4 * 4);
                av.x *= uv.x; av.y *= uv.y; av.z *= uv.z; av.w *= uv.w;
            }
            As[c4*4 + 0][row] = av.x;
            As[c4*4 + 1][row] = av.y;
            As[c4*4 + 2][row] = av.z;
            As[c4*4 + 3][row] = av.w;

            float4 wv = *(const float4*)(W + (size_t)(n0 + row) * Kd + k0 + c4 * 4);
            Ws[c4*4 + 0][row] = wv.x;
            Ws[c4*4 + 1][row] = wv.y;
            Ws[c4*4 + 2][row] = wv.z;
            Ws[c4*4 + 3][row] = wv.w;
        }
        __syncthreads();

        #pragma unroll
        for (int kk = 0; kk < GBK; ++kk) {
            float af[8], wf[8];
            #pragma unroll
            for (int j = 0; j < 8; ++j) af[j] = As[kk][ty * 8 + j];
            #pragma unroll
            for (int j = 0; j < 8; ++j) wf[j] = Ws[kk][tx * 8 + j];
            #pragma unroll
            for (int r = 0; r < 8; ++r)
                #pragma unroll
                for (int c = 0; c < 8; ++c)
                    acc[r][c] += af[r] * wf[c];
        }
        __syncthreads();
    }

    // epilogue
    #pragma unroll
    for (int r = 0; r < 8; ++r) {
        int m = m0 + ty * 8 + r;
        #pragma unroll
        for (int c = 0; c < 8; ++c) {
            int n = n0 + tx * 8 + c;
            float v = acc[r][c];
            if (epi == 1) v = gelu_tanh(v);
            else if (epi == 2) v += R[(size_t)m * Nout + n];
            C[(size_t)m * Nout + n] = v;
        }
    }
}

// ---------------- attention (flash-style, fp32) ----------------
// grid: (TOT/16, N, B); 128 threads
#define ABM 16
#define ABN 32
#define APAD 132

__global__ __launch_bounds__(128)
void attn_kernel(const float* __restrict__ q, const float* __restrict__ k,
                 const float* __restrict__ v, float* __restrict__ enc)
{
    int b  = blockIdx.z;
    int n  = blockIdx.y;
    int kk = n / GC;
    int t0 = blockIdx.x * ABM;

    __shared__ float qs[ABM][APAD];
    __shared__ float ks[ABN][APAD];
    __shared__ float vs[ABN][APAD];
    __shared__ float ps[ABM][ABN];
    __shared__ float mrow[ABM], lrow[ABM], alph[ABM];

    int tid = threadIdx.x;

    // load q tile: 16 rows x 128 = 512 float4
    for (int idx = tid; idx < ABM * 32; idx += 128) {
        int r = idx >> 5, c4 = idx & 31;
        float4 val = *(const float4*)(q + (((size_t)b * TOTC + t0 + r) * NC + n) * HC + c4 * 4);
        *(float4*)&qs[r][c4 * 4] = val;
    }
    if (tid < ABM) { mrow[tid] = -FLT_MAX; lrow[tid] = 0.f; }

    float accv[16];
    #pragma unroll
    for (int j = 0; j < 16; ++j) accv[j] = 0.f;
    int r_own = tid >> 3, dseg = tid & 7;

    __syncthreads();

    int smax = t0 + ABM;   // causal: s <= t0+15
    for (int s0 = 0; s0 < smax; s0 += ABN) {
        // load k/v tiles
        for (int idx = tid; idx < ABN * 32; idx += 128) {
            int r = idx >> 5, c4 = idx & 31;
            size_t goff = (((size_t)b * TOTC + s0 + r) * KC + kk) * HC + c4 * 4;
            *(float4*)&ks[r][c4 * 4] = *(const float4*)(k + goff);
            *(float4*)&vs[r][c4 * 4] = *(const float4*)(v + goff);
        }
        __syncthreads();

        // scores: thread -> s = tid&31, rows {rb, rb+4, rb+8, rb+12}
        {
            int sI = tid & 31, rb = tid >> 5;
            float d0 = 0.f, d1 = 0.f, d2 = 0.f, d3 = 0.f;
            #pragma unroll 8
            for (int d = 0; d < HC; ++d) {
                float kv = ks[sI][d];
                d0 += qs[rb      ][d] * kv;
                d1 += qs[rb +  4][d] * kv;
                d2 += qs[rb +  8][d] * kv;
                d3 += qs[rb + 12][d] * kv;
            }
            int sg = s0 + sI;
            ps[rb     ][sI] = (sg <= t0 + rb     ) ? d0 : -FLT_MAX;
            ps[rb +  4][sI] = (sg <= t0 + rb +  4) ? d1 : -FLT_MAX;
            ps[rb +  8][sI] = (sg <= t0 + rb +  8) ? d2 : -FLT_MAX;
            ps[rb + 12][sI] = (sg <= t0 + rb + 12) ? d3 : -FLT_MAX;
        }
        __syncthreads();

        // online softmax: 8 threads per row (same warp segment)
        {
            int r = tid >> 3, l8 = tid & 7;
            float mold = mrow[r];
            float lold = lrow[r];
            float mx = -FLT_MAX;
            #pragma unroll
            for (int j = 0; j < 4; ++j) mx = fmaxf(mx, ps[r][l8 + 8 * j]);
            #pragma unroll
            for (int o = 1; o < 8; o <<= 1) mx = fmaxf(mx, __shfl_xor_sync(0xffffffffu, mx, o));
            float mnew = fmaxf(mold, mx);
            float a = expf(mold - mnew);     // mold=-FLT_MAX -> 0
            float se = 0.f;
            #pragma unroll
            for (int j = 0; j < 4; ++j) {
                float e = expf(ps[r][l8 + 8 * j] - mnew);
                ps[r][l8 + 8 * j] = e;
                se += e;
            }
            #pragma unroll
            for (int o = 1; o < 8; o <<= 1) se += __shfl_xor_sync(0xffffffffu, se, o);
            // all 8 lanes write identical values (benign)
            mrow[r] = mnew;
            lrow[r] = lold * a + se;
            alph[r] = a;
        }
        __syncthreads();

        // accumulate: thread owns (r_own, d in [dseg*16, dseg*16+16))
        {
            float a = alph[r_own];
            #pragma unroll
            for (int j = 0; j < 16; ++j) accv[j] *= a;
            for (int s = 0; s < ABN; ++s) {
                float p = ps[r_own][s];
                const float* vp = &vs[s][dseg * 16];
                #pragma unroll
                for (int j = 0; j < 16; ++j) accv[j] += p * vp[j];
            }
        }
        __syncthreads();
    }

    float inv = 1.0f / lrow[r_own];
    float* op = enc + (((size_t)b * TOTC + t0 + r_own) * NC + n) * HC + dseg * 16;
    #pragma unroll
    for (int j = 0; j < 16; ++j) op[j] = accv[j] * inv;
}

// ---------------- host ----------------
extern "C" void kernel_launch(void* const* d_in, const int* in_sizes, int n_in,
                              void* d_out, int out_size)
{
    (void)in_sizes; (void)n_in; (void)out_size;
    const float* x0  = (const float*)d_in[0];
    const float* x1  = (const float*)d_in[1];
    const int*   pos = (const int*)  d_in[2];
    // d_in[3] = mask (causal; encoded analytically)
    const float* q0w = (const float*)d_in[4];
    const float* q1w = (const float*)d_in[5];
    const float* k0w = (const float*)d_in[6];
    const float* k1w = (const float*)d_in[7];
    const float* v0w = (const float*)d_in[8];
    const float* v1w = (const float*)d_in[9];
    const float* o0w = (const float*)d_in[10];
    const float* o1w = (const float*)d_in[11];
    const float* gt0 = (const float*)d_in[12];
    const float* gt1 = (const float*)d_in[13];
    const float* up0 = (const float*)d_in[14];
    const float* up1 = (const float*)d_in[15];
    const float* dw0 = (const float*)d_in[16];
    const float* dw1 = (const float*)d_in[17];
    const float* pa0 = (const float*)d_in[18];
    const float* pa1 = (const float*)d_in[19];
    const float* pf0 = (const float*)d_in[20];
    const float* pf1 = (const float*)d_in[21];
    float* out = (float*)d_out;

    float *pre, *qb, *kb, *vb, *enc, *res, *hid, *gate, *up;
    cudaGetSymbolAddress((void**)&pre,  g_pre);
    cudaGetSymbolAddress((void**)&qb,   g_q);
    cudaGetSymbolAddress((void**)&kb,   g_k);
    cudaGetSymbolAddress((void**)&vb,   g_v);
    cudaGetSymbolAddress((void**)&enc,  g_enc);
    cudaGetSymbolAddress((void**)&res,  g_res);
    cudaGetSymbolAddress((void**)&hid,  g_hid);
    cudaGetSymbolAddress((void**)&gate, g_gate);
    cudaGetSymbolAddress((void**)&up,   g_up);

    // 1. pre-attn rmsnorm (per stream)
    rmsnorm_kernel<<<BB * T0C, 256>>>(x0, pre, pa0, 0, 0);
    rmsnorm_kernel<<<BB * T0C, 256>>>(x1, pre, pa1, 1, 0);

    // 2. QKV projections
    {
        dim3 gq(NHC / GBN, T0C / GBM, 4);
        gemm_kernel<<<gq, 256>>>(pre, q0w, q1w, qb, DC, NHC, 0, 0, 0, 0, 0, 0, 0);
        dim3 gk(KHC / GBN, T0C / GBM, 4);
        gemm_kernel<<<gk, 256>>>(pre, k0w, k1w, kb, DC, KHC, 0, 0, 0, 0, 0, 0, 0);
        gemm_kernel<<<gk, 256>>>(pre, v0w, v1w, vb, DC, KHC, 0, 0, 0, 0, 0, 0, 0);
    }

    // 3. RoPE + q scaling
    rope_kernel<<<BB * TOTC, 512>>>(qb, kb, pos);

    // 4. attention
    {
        dim3 ga(TOTC / ABM, NC, BB);
        attn_kernel<<<ga, 128>>>(qb, kb, vb, enc);
    }

    // 5. O projection + residual add (x)
    {
        dim3 go(DC / GBN, T0C / GBM, 4);
        gemm_kernel<<<go, 256>>>(enc, o0w, o1w, res, NHC, DC, 2, 0, 0, x0, x1, 0, 0);
    }

    // 6. pre-ffw rmsnorm
    rmsnorm_kernel<<<BB * T0C, 256>>>(res, hid, pf0, 0, 1);
    rmsnorm_kernel<<<BB * T0C, 256>>>(res, hid, pf1, 1, 1);

    // 7. gate (gelu epilogue) and up projections
    {
        dim3 gf(FC / GBN, T0C / GBM, 4);
        gemm_kernel<<<gf, 256>>>(hid, gt0, gt1, gate, DC, FC, 1, 0, 0, 0, 0, 0, 0);
        gemm_kernel<<<gf, 256>>>(hid, up0, up1, up,   DC, FC, 0, 0, 0, 0, 0, 0, 0);
    }

    // 8. down projection: A = gate*up fused, + residual, write to output (stream-major)
    {
        dim3 gd(DC / GBN, T0C / GBM, 4);
        gemm_kernel<<<gd, 256>>>(gate, dw0, dw1, out, FC, DC, 2, 1, up, res, res, 1, 1);
    }
}

// round 3
// speedup vs baseline: 1.7148x; 1.7148x over previous
#include <cuda_runtime.h>
#include <cuda_bf16.h>
#include <math.h>
#include <float.h>
#include <stdint.h>

// ---------------- problem constants ----------------
#define BB   2
#define T0C  1024
#define TOTC 2048
#define DC   2048
#define NC   16
#define KC   8
#define HC   128
#define FC   8192
#define NHC  2048   // N*H
#define KHC  1024   // K*H
#define GC   2      // N/K

typedef __nv_bfloat16 bf16;

// ---------------- helpers ----------------
__device__ __forceinline__ uint32_t smem_to_u32(const void* p) {
    uint32_t a;
    asm("{ .reg .u64 t; cvta.to.shared.u64 t, %1; cvt.u32.u64 %0, t; }" : "=r"(a) : "l"(p));
    return a;
}
#define LDSM4(r, addr) \
    asm volatile("ldmatrix.sync.aligned.m8n8.x4.shared.b16 {%0,%1,%2,%3}, [%4];" \
        : "=r"((r)[0]), "=r"((r)[1]), "=r"((r)[2]), "=r"((r)[3]) : "r"(addr))
#define MMA16816(d, a, b0, b1) \
    asm volatile("mma.sync.aligned.m16n8k16.row.col.f32.bf16.bf16.f32 " \
        "{%0,%1,%2,%3},{%4,%5,%6,%7},{%8,%9},{%0,%1,%2,%3};" \
        : "+f"((d)[0]), "+f"((d)[1]), "+f"((d)[2]), "+f"((d)[3]) \
        : "r"((a)[0]), "r"((a)[1]), "r"((a)[2]), "r"((a)[3]), "r"(b0), "r"(b1))
#define CP_ASYNC16(saddr, gaddr) \
    asm volatile("cp.async.cg.shared.global [%0], [%1], 16;" :: "r"(saddr), "l"(gaddr))
#define CP_COMMIT() asm volatile("cp.async.commit_group;" ::: "memory")
#define CP_WAIT(n)  asm volatile("cp.async.wait_group %0;" :: "n"(n) : "memory")

// ---------------- scratch (device globals; no runtime alloc) ----------------
__device__ float g_q   [(size_t)BB*TOTC*NHC];
__device__ float g_k   [(size_t)BB*TOTC*KHC];
__device__ float g_v   [(size_t)BB*TOTC*KHC];
__device__ float g_enc [(size_t)BB*TOTC*NHC];
__device__ float g_res [(size_t)BB*TOTC*DC];
__device__ float g_gate[(size_t)BB*TOTC*FC];
__device__ float g_up  [(size_t)BB*TOTC*FC];

__device__ bf16 g_preh[(size_t)BB*TOTC*DC];
__device__ bf16 g_prel[(size_t)BB*TOTC*DC];
__device__ bf16 g_hidh[(size_t)BB*TOTC*DC];
__device__ bf16 g_hidl[(size_t)BB*TOTC*DC];
__device__ bf16 g_ench[(size_t)BB*TOTC*NHC];
__device__ bf16 g_encl[(size_t)BB*TOTC*NHC];
__device__ bf16 g_guh [(size_t)BB*TOTC*FC];
__device__ bf16 g_gul [(size_t)BB*TOTC*FC];
__device__ bf16 g_wh  [125829120];
__device__ bf16 g_wl  [125829120];

// ---------------- elementwise helpers ----------------
__device__ __forceinline__ float gelu_tanh(float x) {
    float x3 = x * x * x;
    return 0.5f * x * (1.0f + tanhf(0.7978845608028654f * (x + 0.044715f * x3)));
}
__device__ __forceinline__ void split_store(float v, bf16* h, bf16* l) {
    bf16 hh = __float2bfloat16(v);
    *h = hh;
    *l = __float2bfloat16(v - __bfloat162float(hh));
}

__global__ void cvt_split_kernel(const float* __restrict__ src,
                                 bf16* __restrict__ h, bf16* __restrict__ l, int n)
{
    int i = (blockIdx.x * 256 + threadIdx.x) * 4;
    if (i >= n) return;
    float4 v = *(const float4*)(src + i);
    split_store(v.x, h + i + 0, l + i + 0);
    split_store(v.y, h + i + 1, l + i + 1);
    split_store(v.z, h + i + 2, l + i + 2);
    split_store(v.w, h + i + 3, l + i + 3);
}

__global__ void gelu_mul_split_kernel(const float* __restrict__ gate, const float* __restrict__ up,
                                      bf16* __restrict__ h, bf16* __restrict__ l, int n)
{
    int i = (blockIdx.x * 256 + threadIdx.x) * 4;
    if (i >= n) return;
    float4 g = *(const float4*)(gate + i);
    float4 u = *(const float4*)(up + i);
    split_store(g.x * u.x, h + i + 0, l + i + 0);
    split_store(g.y * u.y, h + i + 1, l + i + 1);
    split_store(g.z * u.z, h + i + 2, l + i + 2);
    split_store(g.w * u.w, h + i + 3, l + i + 3);
}

// ---------------- rmsnorm (writes bf16 hi/lo split) ----------------
__global__ void rmsnorm_kernel(const float* __restrict__ src,
                               bf16* __restrict__ dsth, bf16* __restrict__ dstl,
                               const float* __restrict__ scale, int istream, int srcmode)
{
    int row = blockIdx.x;               // 0 .. B*T0-1
    int b = row / T0C, t = row % T0C;
    size_t crow = (size_t)b * TOTC + (size_t)istream * T0C + t;
    const float* s = src + (srcmode ? crow : (size_t)row) * DC;
    bf16* oh = dsth + crow * DC;
    bf16* ol = dstl + crow * DC;

    __shared__ float red[256];
    float ss = 0.f;
    for (int d = threadIdx.x; d < DC; d += 256) { float v = s[d]; ss += v * v; }
    red[threadIdx.x] = ss;
    __syncthreads();
    for (int st = 128; st > 0; st >>= 1) {
        if (threadIdx.x < st) red[threadIdx.x] += red[threadIdx.x + st];
        __syncthreads();
    }
    float inv = rsqrtf(red[0] * (1.0f / DC) + 1e-6f);
    for (int d = threadIdx.x; d < DC; d += 256) {
        float v = s[d] * inv * (1.0f + scale[d]);
        split_store(v, oh + d, ol + d);
    }
}

// ---------------- rope ----------------
__global__ void rope_kernel(float* __restrict__ q, float* __restrict__ k,
                            const int* __restrict__ positions)
{
    int row = blockIdx.x;                       // b*TOT + t
    float pos = (float)positions[row];
    const float QSCALE = 0.08838834764831845f;  // 128^-0.5
    for (int w = threadIdx.x; w < (NC + KC) * 64; w += blockDim.x) {
        int head = w >> 6;
        int j = w & 63;
        float ts = powf(10000.0f, (float)j * (1.0f / 64.0f));
        float rad = pos / ts;
        float sn, cs;
        sincosf(rad, &sn, &cs);
        if (head < NC) {
            float* p = q + ((size_t)row * NC + head) * HC;
            float x1 = p[j], x2 = p[j + 64];
            p[j]      = (x1 * cs - x2 * sn) * QSCALE;
            p[j + 64] = (x2 * cs + x1 * sn) * QSCALE;
        } else {
            float* p = k + ((size_t)row * KC + (head - NC)) * HC;
            float x1 = p[j], x2 = p[j + 64];
            p[j]      = x1 * cs - x2 * sn;
            p[j + 64] = x2 * cs + x1 * sn;
        }
    }
}

// ---------------- mma.sync GEMM: C = A @ W^T (+epilogue), bf16x3 split ----------------
// A hi/lo: (concat rows, Kd) bf16 K-major. W hi/lo per stream: (Nout, Kd) bf16 K-major.
// z = i*2 + b. epi: 0 none, 1 gelu, 2 +residual.
// resmode 0: R per-stream ptr (R0/R1 + b*T0*Nout); 1: concat ptr R0.
// outmode 0: concat-time rows; 1: stream-major rows (out0|out1).
#define GBM 128
#define GBN 128
#define GBK 32
#define STAGES 3
#define ROWB   80                    // padded row bytes (32 bf16 -> 64B + 16B pad)
#define TILE_B (GBM * ROWB)          // 10240
#define STAGE_B (4 * TILE_B)         // Ah, Al, Wh, Wl
#define TC_SMEM_BYTES (STAGES * STAGE_B)   // 122880

__global__ __launch_bounds__(256, 1)
void gemm_tc(const bf16* __restrict__ Ah_, const bf16* __restrict__ Al_,
             const bf16* __restrict__ W0h, const bf16* __restrict__ W0l,
             const bf16* __restrict__ W1h, const bf16* __restrict__ W1l,
             float* __restrict__ C_, int Kd, int Nout, int epi,
             const float* __restrict__ R0, const float* __restrict__ R1,
             int resmode, int outmode)
{
    extern __shared__ char smem[];
    const uint32_t s0 = smem_to_u32(smem);

    const int tid = threadIdx.x;
    const int lane = tid & 31, warp = tid >> 5;
    const int wm = warp >> 2, wn = warp & 3;      // warp tile: 64 (m) x 32 (n)

    const int z = blockIdx.z, i = z >> 1, b = z & 1;
    const size_t arow0 = (size_t)b * TOTC + (size_t)i * T0C;
    const bf16* Ah = Ah_ + arow0 * Kd;
    const bf16* Al = Al_ + arow0 * Kd;
    const bf16* Wh = i ? W1h : W0h;
    const bf16* Wl = i ? W1l : W0l;
    float* C = (outmode == 0) ? (C_ + arow0 * (size_t)Nout)
                              : (C_ + ((size_t)i * BB * T0C + (size_t)b * T0C) * (size_t)Nout);
    const float* R = 0;
    if (epi == 2) R = (resmode == 0) ? ((i ? R1 : R0) + (size_t)b * T0C * Nout)
                                     : (R0 + arow0 * (size_t)Nout);

    const int m0 = blockIdx.y * GBM, n0 = blockIdx.x * GBN;

    // cp.async slot for this thread (8 chunks of 16B per stage)
    // idx -> tile (0:Ah 1:Al 2:Wh 3:Wl), row (0..127), c (0..3)
    const int nk = Kd / GBK;

    #define ISSUE_STAGE(cc) do {                                                 \
        int kk0 = (cc) * GBK;                                                    \
        uint32_t sbase = s0 + ((cc) % STAGES) * STAGE_B;                         \
        _Pragma("unroll")                                                        \
        for (int it = 0; it < 8; ++it) {                                         \
            int idx = tid + it * 256;                                            \
            int tile = idx >> 9;                                                 \
            int cid = idx & 511;                                                 \
            int row = cid >> 2, cch = cid & 3;                                   \
            uint32_t sa = sbase + tile * TILE_B + row * ROWB + cch * 16;         \
            const bf16* gp;                                                      \
            if (tile == 0)      gp = Ah + (size_t)(m0 + row) * Kd + kk0 + cch*8; \
            else if (tile == 1) gp = Al + (size_t)(m0 + row) * Kd + kk0 + cch*8; \
            else if (tile == 2) gp = Wh + (size_t)(n0 + row) * Kd + kk0 + cch*8; \
            else                gp = Wl + (size_t)(n0 + row) * Kd + kk0 + cch*8; \
            CP_ASYNC16(sa, gp);                                                  \
        }                                                                        \
        CP_COMMIT();                                                             \
    } while (0)

    float acc[4][4][4];
    #pragma unroll
    for (int mf = 0; mf < 4; ++mf)
        #pragma unroll
        for (int nf = 0; nf < 4; ++nf)
            #pragma unroll
            for (int r = 0; r < 4; ++r) acc[mf][nf][r] = 0.f;

    // per-lane ldmatrix row offsets
    const int a_row = wm * 64 + (lane & 15);          // + mf*16
    const int a_cj  = lane >> 4;                      // 0/1 -> +8 k
    const int b_row = wn * 32 + (lane & 7) + ((lane >> 4) & 1) * 8;  // + nf2*16
    const int b_cj  = (lane >> 3) & 1;                // 0/1 -> +8 k

    ISSUE_STAGE(0);
    ISSUE_STAGE(1);

    for (int c = 0; c < nk; ++c) {
        if (c + 2 < nk) { ISSUE_STAGE(c + 2); CP_WAIT(2); }
        else if (c + 1 < nk) CP_WAIT(1);
        else CP_WAIT(0);
        __syncthreads();

        uint32_t sbase = s0 + (c % STAGES) * STAGE_B;
        uint32_t aH = sbase, aL = sbase + TILE_B;
        uint32_t bH = sbase + 2 * TILE_B, bL = sbase + 3 * TILE_B;

        #pragma unroll
        for (int ks = 0; ks < 2; ++ks) {
            uint32_t ah[4][4], al[4][4], bh[2][4], bl[2][4];
            uint32_t aoff = (uint32_t)(a_row * ROWB + (ks * 2 + a_cj) * 16);
            #pragma unroll
            for (int mf = 0; mf < 4; ++mf) {
                LDSM4(ah[mf], aH + aoff + mf * (16 * ROWB));
                LDSM4(al[mf], aL + aoff + mf * (16 * ROWB));
            }
            uint32_t boff = (uint32_t)(b_row * ROWB + (ks * 2 + b_cj) * 16);
            #pragma unroll
            for (int nf2 = 0; nf2 < 2; ++nf2) {
                LDSM4(bh[nf2], bH + boff + nf2 * (16 * ROWB));
                LDSM4(bl[nf2], bL + boff + nf2 * (16 * ROWB));
            }
            #pragma unroll
            for (int mf = 0; mf < 4; ++mf) {
                #pragma unroll
                for (int nf = 0; nf < 4; ++nf) {
                    uint32_t b0h = bh[nf >> 1][(nf & 1) * 2];
                    uint32_t b1h = bh[nf >> 1][(nf & 1) * 2 + 1];
                    uint32_t b0l = bl[nf >> 1][(nf & 1) * 2];
                    uint32_t b1l = bl[nf >> 1][(nf & 1) * 2 + 1];
                    MMA16816(acc[mf][nf], ah[mf], b0h, b1h);
                    MMA16816(acc[mf][nf], al[mf], b0h, b1h);
                    MMA16816(acc[mf][nf], ah[mf], b0l, b1l);
                }
            }
        }
        __syncthreads();
    }

    // epilogue
    #pragma unroll
    for (int mf = 0; mf < 4; ++mf) {
        int r0 = m0 + wm * 64 + mf * 16 + (lane >> 2);
        #pragma unroll
        for (int nf = 0; nf < 4; ++nf) {
            int col = n0 + wn * 32 + nf * 8 + (lane & 3) * 2;
            float2 v0 = make_float2(acc[mf][nf][0], acc[mf][nf][1]);
            float2 v1 = make_float2(acc[mf][nf][2], acc[mf][nf][3]);
            if (epi == 1) {
                v0.x = gelu_tanh(v0.x); v0.y = gelu_tanh(v0.y);
                v1.x = gelu_tanh(v1.x); v1.y = gelu_tanh(v1.y);
            } else if (epi == 2) {
                float2 r4a = *(const float2*)(R + (size_t)r0 * Nout + col);
                float2 r4b = *(const float2*)(R + (size_t)(r0 + 8) * Nout + col);
                v0.x += r4a.x; v0.y += r4a.y;
                v1.x += r4b.x; v1.y += r4b.y;
            }
            *(float2*)(C + (size_t)r0 * Nout + col)       = v0;
            *(float2*)(C + (size_t)(r0 + 8) * Nout + col) = v1;
        }
    }
}

// ---------------- attention (flash-style, fp32) ----------------
#define ABM 16
#define ABN 32
#define APAD 132

__global__ __launch_bounds__(128)
void attn_kernel(const float* __restrict__ q, const float* __restrict__ k,
                 const float* __restrict__ v, float* __restrict__ enc)
{
    int b  = blockIdx.z;
    int n  = blockIdx.y;
    int kk = n / GC;
    int t0 = blockIdx.x * ABM;

    __shared__ float qs[ABM][APAD];
    __shared__ float ks[ABN][APAD];
    __shared__ float vs[ABN][APAD];
    __shared__ float ps[ABM][ABN];
    __shared__ float mrow[ABM], lrow[ABM], alph[ABM];

    int tid = threadIdx.x;

    for (int idx = tid; idx < ABM * 32; idx += 128) {
        int r = idx >> 5, c4 = idx & 31;
        float4 val = *(const float4*)(q + (((size_t)b * TOTC + t0 + r) * NC + n) * HC + c4 * 4);
        *(float4*)&qs[r][c4 * 4] = val;
    }
    if (tid < ABM) { mrow[tid] = -FLT_MAX; lrow[tid] = 0.f; }

    float accv[16];
    #pragma unroll
    for (int j = 0; j < 16; ++j) accv[j] = 0.f;
    int r_own = tid >> 3, dseg = tid & 7;

    __syncthreads();

    int smax = t0 + ABM;
    for (int s0 = 0; s0 < smax; s0 += ABN) {
        for (int idx = tid; idx < ABN * 32; idx += 128) {
            int r = idx >> 5, c4 = idx & 31;
            size_t goff = (((size_t)b * TOTC + s0 + r) * KC + kk) * HC + c4 * 4;
            *(float4*)&ks[r][c4 * 4] = *(const float4*)(k + goff);
            *(float4*)&vs[r][c4 * 4] = *(const float4*)(v + goff);
        }
        __syncthreads();

        {
            int sI = tid & 31, rb = tid >> 5;
            float d0 = 0.f, d1 = 0.f, d2 = 0.f, d3 = 0.f;
            #pragma unroll 8
            for (int d = 0; d < HC; ++d) {
                float kv = ks[sI][d];
                d0 += qs[rb      ][d] * kv;
                d1 += qs[rb +  4][d] * kv;
                d2 += qs[rb +  8][d] * kv;
                d3 += qs[rb + 12][d] * kv;
            }
            int sg = s0 + sI;
            ps[rb     ][sI] = (sg <= t0 + rb     ) ? d0 : -FLT_MAX;
            ps[rb +  4][sI] = (sg <= t0 + rb +  4) ? d1 : -FLT_MAX;
            ps[rb +  8][sI] = (sg <= t0 + rb +  8) ? d2 : -FLT_MAX;
            ps[rb + 12][sI] = (sg <= t0 + rb + 12) ? d3 : -FLT_MAX;
        }
        __syncthreads();

        {
            int r = tid >> 3, l8 = tid & 7;
            float mold = mrow[r];
            float lold = lrow[r];
            float mx = -FLT_MAX;
            #pragma unroll
            for (int j = 0; j < 4; ++j) mx = fmaxf(mx, ps[r][l8 + 8 * j]);
            #pragma unroll
            for (int o = 1; o < 8; o <<= 1) mx = fmaxf(mx, __shfl_xor_sync(0xffffffffu, mx, o));
            float mnew = fmaxf(mold, mx);
            float a = expf(mold - mnew);
            float se = 0.f;
            #pragma unroll
            for (int j = 0; j < 4; ++j) {
                float e = expf(ps[r][l8 + 8 * j] - mnew);
                ps[r][l8 + 8 * j] = e;
                se += e;
            }
            #pragma unroll
            for (int o = 1; o < 8; o <<= 1) se += __shfl_xor_sync(0xffffffffu, se, o);
            mrow[r] = mnew;
            lrow[r] = lold * a + se;
            alph[r] = a;
        }
        __syncthreads();

        {
            float a = alph[r_own];
            #pragma unroll
            for (int j = 0; j < 16; ++j) accv[j] *= a;
            for (int s = 0; s < ABN; ++s) {
                float p = ps[r_own][s];
                const float* vp = &vs[s][dseg * 16];
                #pragma unroll
                for (int j = 0; j < 16; ++j) accv[j] += p * vp[j];
            }
        }
        __syncthreads();
    }

    float inv = 1.0f / lrow[r_own];
    float* op = enc + (((size_t)b * TOTC + t0 + r_own) * NC + n) * HC + dseg * 16;
    #pragma unroll
    for (int j = 0; j < 16; ++j) op[j] = accv[j] * inv;
}

// ---------------- host ----------------
extern "C" void kernel_launch(void* const* d_in, const int* in_sizes, int n_in,
                              void* d_out, int out_size)
{
    (void)in_sizes; (void)n_in; (void)out_size;
    const float* x0  = (const float*)d_in[0];
    const float* x1  = (const float*)d_in[1];
    const int*   pos = (const int*)  d_in[2];
    const float* q0w = (const float*)d_in[4];
    const float* q1w = (const float*)d_in[5];
    const float* k0w = (const float*)d_in[6];
    const float* k1w = (const float*)d_in[7];
    const float* v0w = (const float*)d_in[8];
    const float* v1w = (const float*)d_in[9];
    const float* o0w = (const float*)d_in[10];
    const float* o1w = (const float*)d_in[11];
    const float* gt0 = (const float*)d_in[12];
    const float* gt1 = (const float*)d_in[13];
    const float* up0 = (const float*)d_in[14];
    const float* up1 = (const float*)d_in[15];
    const float* dw0 = (const float*)d_in[16];
    const float* dw1 = (const float*)d_in[17];
    const float* pa0 = (const float*)d_in[18];
    const float* pa1 = (const float*)d_in[19];
    const float* pf0 = (const float*)d_in[20];
    const float* pf1 = (const float*)d_in[21];
    float* out = (float*)d_out;

    float *qb, *kb, *vb, *enc, *res, *gate, *up;
    bf16 *preh, *prel, *hidh, *hidl, *ench, *encl, *guh, *gul, *wh, *wl;
    cudaGetSymbolAddress((void**)&qb,   g_q);
    cudaGetSymbolAddress((void**)&kb,   g_k);
    cudaGetSymbolAddress((void**)&vb,   g_v);
    cudaGetSymbolAddress((void**)&enc,  g_enc);
    cudaGetSymbolAddress((void**)&res,  g_res);
    cudaGetSymbolAddress((void**)&gate, g_gate);
    cudaGetSymbolAddress((void**)&up,   g_up);
    cudaGetSymbolAddress((void**)&preh, g_preh);
    cudaGetSymbolAddress((void**)&prel, g_prel);
    cudaGetSymbolAddress((void**)&hidh, g_hidh);
    cudaGetSymbolAddress((void**)&hidl, g_hidl);
    cudaGetSymbolAddress((void**)&ench, g_ench);
    cudaGetSymbolAddress((void**)&encl, g_encl);
    cudaGetSymbolAddress((void**)&guh,  g_guh);
    cudaGetSymbolAddress((void**)&gul,  g_gul);
    cudaGetSymbolAddress((void**)&wh,   g_wh);
    cudaGetSymbolAddress((void**)&wl,   g_wl);

    cudaFuncSetAttribute(gemm_tc, cudaFuncAttributeMaxDynamicSharedMemorySize, TC_SMEM_BYTES);

    // weight offsets in the packed hi/lo buffers
    const size_t QN = (size_t)NHC * DC;
    const size_t KN = (size_t)KHC * DC;
    const size_t FN = (size_t)FC * DC;
    const size_t oq0 = 0,         oq1 = oq0 + QN;
    const size_t ok0 = oq1 + QN,  ok1 = ok0 + KN;
    const size_t ov0 = ok1 + KN,  ov1 = ov0 + KN;
    const size_t oo0 = ov1 + KN,  oo1 = oo0 + QN;
    const size_t og0 = oo1 + QN,  og1 = og0 + FN;
    const size_t ou0 = og1 + FN,  ou1 = ou0 + FN;
    const size_t od0 = ou1 + FN,  od1 = od0 + FN;

    // 0. weight fp32 -> bf16 hi/lo
    cvt_split_kernel<<<(int)(QN / 1024), 256>>>(q0w, wh + oq0, wl + oq0, (int)QN);
    cvt_split_kernel<<<(int)(QN / 1024), 256>>>(q1w, wh + oq1, wl + oq1, (int)QN);
    cvt_split_kernel<<<(int)(KN / 1024), 256>>>(k0w, wh + ok0, wl + ok0, (int)KN);
    cvt_split_kernel<<<(int)(KN / 1024), 256>>>(k1w, wh + ok1, wl + ok1, (int)KN);
    cvt_split_kernel<<<(int)(KN / 1024), 256>>>(v0w, wh + ov0, wl + ov0, (int)KN);
    cvt_split_kernel<<<(int)(KN / 1024), 256>>>(v1w, wh + ov1, wl + ov1, (int)KN);
    cvt_split_kernel<<<(int)(QN / 1024), 256>>>(o0w, wh + oo0, wl + oo0, (int)QN);
    cvt_split_kernel<<<(int)(QN / 1024), 256>>>(o1w, wh + oo1, wl + oo1, (int)QN);
    cvt_split_kernel<<<(int)(FN / 1024), 256>>>(gt0, wh + og0, wl + og0, (int)FN);
    cvt_split_kernel<<<(int)(FN / 1024), 256>>>(gt1, wh + og1, wl + og1, (int)FN);
    cvt_split_kernel<<<(int)(FN / 1024), 256>>>(up0, wh + ou0, wl + ou0, (int)FN);
    cvt_split_kernel<<<(int)(FN / 1024), 256>>>(up1, wh + ou1, wl + ou1, (int)FN);
    cvt_split_kernel<<<(int)(FN / 1024), 256>>>(dw0, wh + od0, wl + od0, (int)FN);
    cvt_split_kernel<<<(int)(FN / 1024), 256>>>(dw1, wh + od1, wl + od1, (int)FN);

    // 1. pre-attn rmsnorm -> bf16 hi/lo
    rmsnorm_kernel<<<BB * T0C, 256>>>(x0, preh, prel, pa0, 0, 0);
    rmsnorm_kernel<<<BB * T0C, 256>>>(x1, preh, prel, pa1, 1, 0);

    // 2. QKV projections (mma.sync)
    {
        dim3 gq(NHC / 128, T0C / 128, 4);
        gemm_tc<<<gq, 256, TC_SMEM_BYTES>>>(preh, prel, wh + oq0, wl + oq0, wh + oq1, wl + oq1,
                                            qb, DC, NHC, 0, 0, 0, 0, 0);
        dim3 gk(KHC / 128, T0C / 128, 4);
        gemm_tc<<<gk, 256, TC_SMEM_BYTES>>>(preh, prel, wh + ok0, wl + ok0, wh + ok1, wl + ok1,
                                            kb, DC, KHC, 0, 0, 0, 0, 0);
        gemm_tc<<<gk, 256, TC_SMEM_BYTES>>>(preh, prel, wh + ov0, wl + ov0, wh + ov1, wl + ov1,
                                            vb, DC, KHC, 0, 0, 0, 0, 0);
    }

    // 3. RoPE + q scaling
    rope_kernel<<<BB * TOTC, 512>>>(qb, kb, pos);

    // 4. attention
    {
        dim3 ga(TOTC / ABM, NC, BB);
        attn_kernel<<<ga, 128>>>(qb, kb, vb, enc);
    }

    // 5. enc -> bf16 hi/lo ; O projection + residual
    {
        const int EN = BB * TOTC * NHC;
        cvt_split_kernel<<<EN / 1024, 256>>>(enc, ench, encl, EN);
        dim3 go(DC / 128, T0C / 128, 4);
        gemm_tc<<<go, 256, TC_SMEM_BYTES>>>(ench, encl, wh + oo0, wl + oo0, wh + oo1, wl + oo1,
                                            res, NHC, DC, 2, x0, x1, 0, 0);
    }

    // 6. pre-ffw rmsnorm -> bf16 hi/lo
    rmsnorm_kernel<<<BB * T0C, 256>>>(res, hidh, hidl, pf0, 0, 1);
    rmsnorm_kernel<<<BB * T0C, 256>>>(res, hidh, hidl, pf1, 1, 1);

    // 7. gate (gelu epilogue) and up projections
    {
        dim3 gf(FC / 128, T0C / 128, 4);
        gemm_tc<<<gf, 256, TC_SMEM_BYTES>>>(hidh, hidl, wh + og0, wl + og0, wh + og1, wl + og1,
                                            gate, DC, FC, 1, 0, 0, 0, 0);
        gemm_tc<<<gf, 256, TC_SMEM_BYTES>>>(hidh, hidl, wh + ou0, wl + ou0, wh + ou1, wl + ou1,
                                            up, DC, FC, 0, 0, 0, 0, 0);
    }

    // 8. gu = gelu(gate)*up -> bf16 hi/lo ; down projection + residual -> out
    {
        const int GN = BB * TOTC * FC;
        gelu_mul_split_kernel<<<GN / 1024, 256>>>(gate, up, guh, gul, GN);
        dim3 gd(DC / 128, T0C / 128, 4);
        gemm_tc<<<gd, 256, TC_SMEM_BYTES>>>(guh, gul, wh + od0, wl + od0, wh + od1, wl + od1,
                                            out, FC, DC, 2, res, 0, 1, 1);
    }
}

// round 4
// speedup vs baseline: 3.1855x; 1.8577x over previous
#include <cuda_runtime.h>
#include <cuda_bf16.h>
#include <math.h>
#include <float.h>
#include <stdint.h>

// ---------------- problem constants ----------------
#define BB   2
#define T0C  1024
#define TOTC 2048
#define DC   2048
#define NC   16
#define KC   8
#define HC   128
#define FC   8192
#define NHC  2048   // N*H
#define KHC  1024   // K*H
#define GC   2      // N/K

typedef __nv_bfloat16 bf16;

// ---------------- helpers ----------------
__device__ __forceinline__ uint32_t smem_to_u32(const void* p) {
    uint32_t a;
    asm("{ .reg .u64 t; cvta.to.shared.u64 t, %1; cvt.u32.u64 %0, t; }" : "=r"(a) : "l"(p));
    return a;
}
#define LDSM4(r, addr) \
    asm volatile("ldmatrix.sync.aligned.m8n8.x4.shared.b16 {%0,%1,%2,%3}, [%4];" \
        : "=r"((r)[0]), "=r"((r)[1]), "=r"((r)[2]), "=r"((r)[3]) : "r"(addr))
#define LDSM4T(r, addr) \
    asm volatile("ldmatrix.sync.aligned.m8n8.x4.trans.shared.b16 {%0,%1,%2,%3}, [%4];" \
        : "=r"((r)[0]), "=r"((r)[1]), "=r"((r)[2]), "=r"((r)[3]) : "r"(addr))
#define MMA16816(d, a, b0, b1) \
    asm volatile("mma.sync.aligned.m16n8k16.row.col.f32.bf16.bf16.f32 " \
        "{%0,%1,%2,%3},{%4,%5,%6,%7},{%8,%9},{%0,%1,%2,%3};" \
        : "+f"((d)[0]), "+f"((d)[1]), "+f"((d)[2]), "+f"((d)[3]) \
        : "r"((a)[0]), "r"((a)[1]), "r"((a)[2]), "r"((a)[3]), "r"(b0), "r"(b1))
#define CP_ASYNC16(saddr, gaddr) \
    asm volatile("cp.async.cg.shared.global [%0], [%1], 16;" :: "r"(saddr), "l"(gaddr))
#define CP_COMMIT() asm volatile("cp.async.commit_group;" ::: "memory")
#define CP_WAIT(n)  asm volatile("cp.async.wait_group %0;" :: "n"(n) : "memory")

// ---------------- scratch (device globals; no runtime alloc) ----------------
__device__ float g_q   [(size_t)BB*TOTC*NHC];
__device__ float g_k   [(size_t)BB*TOTC*KHC];
__device__ float g_v   [(size_t)BB*TOTC*KHC];
__device__ float g_res [(size_t)BB*TOTC*DC];
__device__ float g_gate[(size_t)BB*TOTC*FC];

__device__ bf16 g_preh[(size_t)BB*TOTC*DC];
__device__ bf16 g_prel[(size_t)BB*TOTC*DC];
__device__ bf16 g_hidh[(size_t)BB*TOTC*DC];
__device__ bf16 g_hidl[(size_t)BB*TOTC*DC];
__device__ bf16 g_ench[(size_t)BB*TOTC*NHC];
__device__ bf16 g_encl[(size_t)BB*TOTC*NHC];
__device__ bf16 g_guh [(size_t)BB*TOTC*FC];
__device__ bf16 g_gul [(size_t)BB*TOTC*FC];
__device__ bf16 g_qh  [(size_t)BB*TOTC*NHC];
__device__ bf16 g_ql  [(size_t)BB*TOTC*NHC];
__device__ bf16 g_kh  [(size_t)BB*TOTC*KHC];
__device__ bf16 g_kl  [(size_t)BB*TOTC*KHC];
__device__ bf16 g_vh  [(size_t)BB*TOTC*KHC];
__device__ bf16 g_vl  [(size_t)BB*TOTC*KHC];
__device__ bf16 g_wh  [125829120];
__device__ bf16 g_wl  [125829120];

// ---------------- elementwise helpers ----------------
__device__ __forceinline__ float gelu_tanh(float x) {
    float x3 = x * x * x;
    return 0.5f * x * (1.0f + tanhf(0.7978845608028654f * (x + 0.044715f * x3)));
}
__device__ __forceinline__ void split_store(float v, bf16* h, bf16* l) {
    bf16 hh = __float2bfloat16(v);
    *h = hh;
    *l = __float2bfloat16(v - __bfloat162float(hh));
}
__device__ __forceinline__ uint32_t pack_split2(float a, float b, uint32_t& lo) {
    bf16 ha = __float2bfloat16(a), hb = __float2bfloat16(b);
    bf16 la = __float2bfloat16(a - __bfloat162float(ha));
    bf16 lb = __float2bfloat16(b - __bfloat162float(hb));
    lo = (uint32_t)__bfloat16_as_ushort(la) | ((uint32_t)__bfloat16_as_ushort(lb) << 16);
    return (uint32_t)__bfloat16_as_ushort(ha) | ((uint32_t)__bfloat16_as_ushort(hb) << 16);
}

// fp32 -> bf16 hi/lo split, 8 elems/thread, vectorized 16B stores
__global__ void cvt_split_kernel(const float* __restrict__ src,
                                 bf16* __restrict__ h, bf16* __restrict__ l, int n)
{
    int i = (blockIdx.x * 256 + threadIdx.x) * 8;
    if (i >= n) return;
    float4 a = *(const float4*)(src + i);
    float4 b = *(const float4*)(src + i + 4);
    uint4 hv, lv;
    hv.x = pack_split2(a.x, a.y, lv.x);
    hv.y = pack_split2(a.z, a.w, lv.y);
    hv.z = pack_split2(b.x, b.y, lv.z);
    hv.w = pack_split2(b.z, b.w, lv.w);
    *(uint4*)(h + i) = hv;
    *(uint4*)(l + i) = lv;
}

// ---------------- rmsnorm (writes bf16 hi/lo split) ----------------
__global__ void rmsnorm_kernel(const float* __restrict__ src,
                               bf16* __restrict__ dsth, bf16* __restrict__ dstl,
                               const float* __restrict__ scale, int istream, int srcmode)
{
    int row = blockIdx.x;               // 0 .. B*T0-1
    int b = row / T0C, t = row % T0C;
    size_t crow = (size_t)b * TOTC + (size_t)istream * T0C + t;
    const float* s = src + (srcmode ? crow : (size_t)row) * DC;
    bf16* oh = dsth + crow * DC;
    bf16* ol = dstl + crow * DC;

    __shared__ float red[256];
    float ss = 0.f;
    for (int d = threadIdx.x; d < DC; d += 256) { float v = s[d]; ss += v * v; }
    red[threadIdx.x] = ss;
    __syncthreads();
    for (int st = 128; st > 0; st >>= 1) {
        if (threadIdx.x < st) red[threadIdx.x] += red[threadIdx.x + st];
        __syncthreads();
    }
    float inv = rsqrtf(red[0] * (1.0f / DC) + 1e-6f);
    for (int d = threadIdx.x; d < DC; d += 256) {
        float v = s[d] * inv * (1.0f + scale[d]);
        split_store(v, oh + d, ol + d);
    }
}

// ---------------- rope + split (q,k roped+split; v split only) ----------------
__global__ void rope_split_kernel(const float* __restrict__ q, const float* __restrict__ k,
                                  const float* __restrict__ v, const int* __restrict__ positions,
                                  bf16* __restrict__ qh, bf16* __restrict__ ql,
                                  bf16* __restrict__ kh, bf16* __restrict__ kl,
                                  bf16* __restrict__ vh, bf16* __restrict__ vl)
{
    int row = blockIdx.x;                       // b*TOT + t
    float pos = (float)positions[row];
    const float QSCALE = 0.08838834764831845f;  // 128^-0.5
    for (int w = threadIdx.x; w < (NC + KC) * 64; w += 256) {
        int head = w >> 6;
        int j = w & 63;
        float ts = powf(10000.0f, (float)j * (1.0f / 64.0f));
        float sn, cs;
        sincosf(pos / ts, &sn, &cs);
        if (head < NC) {
            size_t o = ((size_t)row * NC + head) * HC;
            float x1 = q[o + j], x2 = q[o + j + 64];
            split_store((x1 * cs - x2 * sn) * QSCALE, qh + o + j, ql + o + j);
            split_store((x2 * cs + x1 * sn) * QSCALE, qh + o + j + 64, ql + o + j + 64);
        } else {
            size_t o = ((size_t)row * KC + (head - NC)) * HC;
            float x1 = k[o + j], x2 = k[o + j + 64];
            split_store(x1 * cs - x2 * sn, kh + o + j, kl + o + j);
            split_store(x2 * cs + x1 * sn, kh + o + j + 64, kl + o + j + 64);
        }
    }
    for (int idx = threadIdx.x; idx < KHC; idx += 256) {
        size_t o = (size_t)row * KHC + idx;
        split_store(v[o], vh + o, vl + o);
    }
}

// ---------------- mma.sync GEMM: C = A @ W^T (+epilogue), bf16x3 split ----------------
// epi: 0 none, 1 gelu, 2 +residual, 3 gelu-gate-mul-split (reads G, writes GH/GL)
#define GBM 128
#define GBN 128
#define GBK 32
#define STAGES 3
#define ROWB   80
#define TILE_B (GBM * ROWB)
#define STAGE_B (4 * TILE_B)
#define TC_SMEM_BYTES (STAGES * STAGE_B)   // 122880

__global__ __launch_bounds__(256, 1)
void gemm_tc(const bf16* __restrict__ Ah_, const bf16* __restrict__ Al_,
             const bf16* __restrict__ W0h, const bf16* __restrict__ W0l,
             const bf16* __restrict__ W1h, const bf16* __restrict__ W1l,
             float* __restrict__ C_, int Kd, int Nout, int epi,
             const float* __restrict__ R0, const float* __restrict__ R1,
             int resmode, int outmode,
             const float* __restrict__ G_, bf16* __restrict__ GH_, bf16* __restrict__ GL_)
{
    extern __shared__ char smem[];
    const uint32_t s0 = smem_to_u32(smem);

    const int tid = threadIdx.x;
    const int lane = tid & 31, warp = tid >> 5;
    const int wm = warp >> 2, wn = warp & 3;      // warp tile: 64 (m) x 32 (n)

    const int z = blockIdx.z, i = z >> 1, b = z & 1;
    const size_t arow0 = (size_t)b * TOTC + (size_t)i * T0C;
    const bf16* Ah = Ah_ + arow0 * Kd;
    const bf16* Al = Al_ + arow0 * Kd;
    const bf16* Wh = i ? W1h : W0h;
    const bf16* Wl = i ? W1l : W0l;
    float* C = (outmode == 0) ? (C_ + arow0 * (size_t)Nout)
                              : (C_ + ((size_t)i * BB * T0C + (size_t)b * T0C) * (size_t)Nout);
    const float* R = 0;
    if (epi == 2) R = (resmode == 0) ? ((i ? R1 : R0) + (size_t)b * T0C * Nout)
                                     : (R0 + arow0 * (size_t)Nout);
    const float* G = 0; bf16* GH = 0; bf16* GL = 0;
    if (epi == 3) { G = G_ + arow0 * (size_t)Nout; GH = GH_ + arow0 * (size_t)Nout; GL = GL_ + arow0 * (size_t)Nout; }

    const int m0 = blockIdx.y * GBM, n0 = blockIdx.x * GBN;
    const int nk = Kd / GBK;

    #define ISSUE_STAGE(cc) do {                                                 \
        int kk0 = (cc) * GBK;                                                    \
        uint32_t sbase = s0 + ((cc) % STAGES) * STAGE_B;                         \
        _Pragma("unroll")                                                        \
        for (int it = 0; it < 8; ++it) {                                         \
            int idx = tid + it * 256;                                            \
            int tile = idx >> 9;                                                 \
            int cid = idx & 511;                                                 \
            int row = cid >> 2, cch = cid & 3;                                   \
            uint32_t sa = sbase + tile * TILE_B + row * ROWB + cch * 16;         \
            const bf16* gp;                                                      \
            if (tile == 0)      gp = Ah + (size_t)(m0 + row) * Kd + kk0 + cch*8; \
            else if (tile == 1) gp = Al + (size_t)(m0 + row) * Kd + kk0 + cch*8; \
            else if (tile == 2) gp = Wh + (size_t)(n0 + row) * Kd + kk0 + cch*8; \
            else                gp = Wl + (size_t)(n0 + row) * Kd + kk0 + cch*8; \
            CP_ASYNC16(sa, gp);                                                  \
        }                                                                        \
        CP_COMMIT();                                                             \
    } while (0)

    float acc[4][4][4];
    #pragma unroll
    for (int mf = 0; mf < 4; ++mf)
        #pragma unroll
        for (int nf = 0; nf < 4; ++nf)
            #pragma unroll
            for (int r = 0; r < 4; ++r) acc[mf][nf][r] = 0.f;

    const int a_row = wm * 64 + (lane & 15);
    const int a_cj  = lane >> 4;
    const int b_row = wn * 32 + (lane & 7) + ((lane >> 4) & 1) * 8;
    const int b_cj  = (lane >> 3) & 1;

    ISSUE_STAGE(0);
    ISSUE_STAGE(1);

    for (int c = 0; c < nk; ++c) {
        if (c + 2 < nk) { ISSUE_STAGE(c + 2); CP_WAIT(2); }
        else if (c + 1 < nk) CP_WAIT(1);
        else CP_WAIT(0);
        __syncthreads();

        uint32_t sbase = s0 + (c % STAGES) * STAGE_B;
        uint32_t aH = sbase, aL = sbase + TILE_B;
        uint32_t bH = sbase + 2 * TILE_B, bL = sbase + 3 * TILE_B;

        #pragma unroll
        for (int ks = 0; ks < 2; ++ks) {
            uint32_t ah[4][4], al[4][4], bh[2][4], bl[2][4];
            uint32_t aoff = (uint32_t)(a_row * ROWB + (ks * 2 + a_cj) * 16);
            #pragma unroll
            for (int mf = 0; mf < 4; ++mf) {
                LDSM4(ah[mf], aH + aoff + mf * (16 * ROWB));
                LDSM4(al[mf], aL + aoff + mf * (16 * ROWB));
            }
            uint32_t boff = (uint32_t)(b_row * ROWB + (ks * 2 + b_cj) * 16);
            #pragma unroll
            for (int nf2 = 0; nf2 < 2; ++nf2) {
                LDSM4(bh[nf2], bH + boff + nf2 * (16 * ROWB));
                LDSM4(bl[nf2], bL + boff + nf2 * (16 * ROWB));
            }
            #pragma unroll
            for (int mf = 0; mf < 4; ++mf) {
                #pragma unroll
                for (int nf = 0; nf < 4; ++nf) {
                    uint32_t b0h = bh[nf >> 1][(nf & 1) * 2];
                    uint32_t b1h = bh[nf >> 1][(nf & 1) * 2 + 1];
                    uint32_t b0l = bl[nf >> 1][(nf & 1) * 2];
                    uint32_t b1l = bl[nf >> 1][(nf & 1) * 2 + 1];
                    MMA16816(acc[mf][nf], ah[mf], b0h, b1h);
                    MMA16816(acc[mf][nf], al[mf], b0h, b1h);
                    MMA16816(acc[mf][nf], ah[mf], b0l, b1l);
                }
            }
        }
        __syncthreads();
    }

    // epilogue
    #pragma unroll
    for (int mf = 0; mf < 4; ++mf) {
        int r0 = m0 + wm * 64 + mf * 16 + (lane >> 2);
        #pragma unroll
        for (int nf = 0; nf < 4; ++nf) {
            int col = n0 + wn * 32 + nf * 8 + (lane & 3) * 2;
            float2 v0 = make_float2(acc[mf][nf][0], acc[mf][nf][1]);
            float2 v1 = make_float2(acc[mf][nf][2], acc[mf][nf][3]);
            if (epi == 3) {
                float2 g0 = *(const float2*)(G + (size_t)r0 * Nout + col);
                float2 g1 = *(const float2*)(G + (size_t)(r0 + 8) * Nout + col);
                uint32_t lo0, lo1;
                uint32_t hi0 = pack_split2(v0.x * g0.x, v0.y * g0.y, lo0);
                uint32_t hi1 = pack_split2(v1.x * g1.x, v1.y * g1.y, lo1);
                *(uint32_t*)((char*)GH + ((size_t)r0 * Nout + col) * 2)       = hi0;
                *(uint32_t*)((char*)GL + ((size_t)r0 * Nout + col) * 2)       = lo0;
                *(uint32_t*)((char*)GH + ((size_t)(r0 + 8) * Nout + col) * 2) = hi1;
                *(uint32_t*)((char*)GL + ((size_t)(r0 + 8) * Nout + col) * 2) = lo1;
            } else {
                if (epi == 1) {
                    v0.x = gelu_tanh(v0.x); v0.y = gelu_tanh(v0.y);
                    v1.x = gelu_tanh(v1.x); v1.y = gelu_tanh(v1.y);
                } else if (epi == 2) {
                    float2 r4a = *(const float2*)(R + (size_t)r0 * Nout + col);
                    float2 r4b = *(const float2*)(R + (size_t)(r0 + 8) * Nout + col);
                    v0.x += r4a.x; v0.y += r4a.y;
                    v1.x += r4b.x; v1.y += r4b.y;
                }
                *(float2*)(C + (size_t)r0 * Nout + col)       = v0;
                *(float2*)(C + (size_t)(r0 + 8) * Nout + col) = v1;
            }
        }
    }
}

// ---------------- attention: mma.sync flash kernel, bf16 hi/lo splits ----------------
#define ATT_BM 128
#define ATT_BN 32
#define QROWB 272
#define KROWB 272
#define PROWB 80
#define SQH 0
#define SQL 34816
#define SKV 69632
#define KVTILE 8704
#define SPH 139264
#define SPL 149504
#define ATT_SMEM 159744
#define NEGA (-1e30f)

__global__ __launch_bounds__(256, 1)
void attn_mma_kernel(const bf16* __restrict__ qh, const bf16* __restrict__ ql,
                     const bf16* __restrict__ kh, const bf16* __restrict__ kl,
                     const bf16* __restrict__ vh, const bf16* __restrict__ vl,
                     bf16* __restrict__ ench, bf16* __restrict__ encl)
{
    extern __shared__ char smem[];
    const uint32_t s0u = smem_to_u32(smem);
    const int tid = threadIdx.x, lane = tid & 31, w = tid >> 5;
    const int bq = blockIdx.z;
    const int n = blockIdx.y;
    const int kk = n >> 1;
    const int t0 = ((int)gridDim.x - 1 - (int)blockIdx.x) * ATT_BM;   // big CTAs first
    const size_t bT = (size_t)bq * TOTC;

    // Q tile hi/lo -> smem
    #pragma unroll
    for (int it = 0; it < 16; ++it) {
        int idx = tid + it * 256;
        int tens = idx >> 11, row = (idx >> 4) & 127, ch = idx & 15;
        const bf16* src = (tens ? ql : qh) + ((bT + t0 + row) * NC + n) * HC + ch * 8;
        CP_ASYNC16(s0u + (tens ? SQL : SQH) + row * QROWB + ch * 16, src);
    }
    CP_COMMIT();

    #define LOAD_KV(j) do {                                                        \
        int _bf = (j) & 1; int _s0 = (j) * ATT_BN;                                 \
        _Pragma("unroll")                                                          \
        for (int it = 0; it < 8; ++it) {                                           \
            int idx = tid + it * 256;                                              \
            int tt = idx >> 9, cid = idx & 511, row = cid >> 4, ch = cid & 15;     \
            const bf16* srcp;                                                      \
            if (tt == 0) srcp = kh; else if (tt == 1) srcp = kl;                   \
            else if (tt == 2) srcp = vh; else srcp = vl;                           \
            srcp += ((bT + _s0 + row) * KC + kk) * HC + ch * 8;                    \
            CP_ASYNC16(s0u + SKV + (_bf * 4 + tt) * KVTILE + row * KROWB + ch * 16, srcp); \
        }                                                                          \
        CP_COMMIT();                                                               \
    } while (0)

    const int nb = t0 / ATT_BN + 4;
    LOAD_KV(0);

    const int tw = t0 + w * 16;
    const int r0 = lane >> 2;                 // warp-local rows r0, r0+8
    float oacc[16][4];
    #pragma unroll
    for (int a = 0; a < 16; ++a) { oacc[a][0] = oacc[a][1] = oacc[a][2] = oacc[a][3] = 0.f; }
    float mrow0 = NEGA, mrow1 = NEGA, lrow0 = 0.f, lrow1 = 0.f;

    const uint32_t psh_base = s0u + SPH + (w * 16) * PROWB;
    const uint32_t psl_base = s0u + SPL + (w * 16) * PROWB;

    for (int j = 0; j < nb; ++j) {
        CP_WAIT(0);
        __syncthreads();
        if (j + 1 < nb) LOAD_KV(j + 1);

        const int sblk = j * ATT_BN;
        const int bf = j & 1;
        const uint32_t kH = s0u + SKV + (bf * 4 + 0) * KVTILE;
        const uint32_t kL = s0u + SKV + (bf * 4 + 1) * KVTILE;
        const uint32_t vH = s0u + SKV + (bf * 4 + 2) * KVTILE;
        const uint32_t vL = s0u + SKV + (bf * 4 + 3) * KVTILE;

        if (sblk <= tw + 15) {                 // warp has unmasked rows
            // ---- S = Q K^T (bf16x3) ----
            float sacc[4][4];
            #pragma unroll
            for (int nf = 0; nf < 4; ++nf) { sacc[nf][0]=sacc[nf][1]=sacc[nf][2]=sacc[nf][3]=0.f; }
            const uint32_t aoff_base = (uint32_t)((w * 16 + (lane & 15)) * QROWB + (lane >> 4) * 16);
            const uint32_t brow = (uint32_t)((lane & 7) + ((lane >> 4) & 1) * 8);
            const uint32_t bco  = (uint32_t)(((lane >> 3) & 1) * 16);
            #pragma unroll
            for (int ks = 0; ks < 8; ++ks) {
                uint32_t ah[4], al[4], bh0[4], bh1[4], bl0[4], bl1[4];
                uint32_t aoff = aoff_base + ks * 32;
                LDSM4(ah, s0u + SQH + aoff);
                LDSM4(al, s0u + SQL + aoff);
                uint32_t boff0 = brow * KROWB + ks * 32 + bco;
                uint32_t boff1 = boff0 + 16 * KROWB;
                LDSM4(bh0, kH + boff0); LDSM4(bh1, kH + boff1);
                LDSM4(bl0, kL + boff0); LDSM4(bl1, kL + boff1);
                MMA16816(sacc[0], ah, bh0[0], bh0[1]);
                MMA16816(sacc[0], al, bh0[0], bh0[1]);
                MMA16816(sacc[0], ah, bl0[0], bl0[1]);
                MMA16816(sacc[1], ah, bh0[2], bh0[3]);
                MMA16816(sacc[1], al, bh0[2], bh0[3]);
                MMA16816(sacc[1], ah, bl0[2], bl0[3]);
                MMA16816(sacc[2], ah, bh1[0], bh1[1]);
                MMA16816(sacc[2], al, bh1[0], bh1[1]);
                MMA16816(sacc[2], ah, bl1[0], bl1[1]);
                MMA16816(sacc[3], ah, bh1[2], bh1[3]);
                MMA16816(sacc[3], al, bh1[2], bh1[3]);
                MMA16816(sacc[3], ah, bl1[2], bl1[3]);
            }

            // ---- causal mask (diagonal blocks only) ----
            if (sblk + ATT_BN - 1 > tw) {
                #pragma unroll
                for (int nf = 0; nf < 4; ++nf) {
                    int sg = sblk + nf * 8 + (lane & 3) * 2;
                    int tg0 = tw + r0, tg1 = tg0 + 8;
                    if (sg     > tg0) sacc[nf][0] = NEGA;
                    if (sg + 1 > tg0) sacc[nf][1] = NEGA;
                    if (sg     > tg1) sacc[nf][2] = NEGA;
                    if (sg + 1 > tg1) sacc[nf][3] = NEGA;
                }
            }

            // ---- online softmax ----
            float mx0 = NEGA, mx1 = NEGA;
            #pragma unroll
            for (int nf = 0; nf < 4; ++nf) {
                mx0 = fmaxf(mx0, fmaxf(sacc[nf][0], sacc[nf][1]));
                mx1 = fmaxf(mx1, fmaxf(sacc[nf][2], sacc[nf][3]));
            }
            mx0 = fmaxf(mx0, __shfl_xor_sync(0xffffffffu, mx0, 1));
            mx0 = fmaxf(mx0, __shfl_xor_sync(0xffffffffu, mx0, 2));
            mx1 = fmaxf(mx1, __shfl_xor_sync(0xffffffffu, mx1, 1));
            mx1 = fmaxf(mx1, __shfl_xor_sync(0xffffffffu, mx1, 2));
            float mn0 = fmaxf(mrow0, mx0), mn1 = fmaxf(mrow1, mx1);
            float al0 = __expf(mrow0 - mn0), al1 = __expf(mrow1 - mn1);
            float se0 = 0.f, se1 = 0.f;
            #pragma unroll
            for (int nf = 0; nf < 4; ++nf) {
                float p0 = __expf(sacc[nf][0] - mn0);
                float p1 = __expf(sacc[nf][1] - mn0);
                float p2 = __expf(sacc[nf][2] - mn1);
                float p3 = __expf(sacc[nf][3] - mn1);
                se0 += p0 + p1; se1 += p2 + p3;
                uint32_t pcol = (uint32_t)((nf * 8 + (lane & 3) * 2) * 2);
                uint32_t lo0, lo1;
                uint32_t hi0 = pack_split2(p0, p1, lo0);
                uint32_t hi1 = pack_split2(p2, p3, lo1);
                *(uint32_t*)(smem + (psh_base - s0u) + r0 * PROWB + pcol)       = hi0;
                *(uint32_t*)(smem + (psl_base - s0u) + r0 * PROWB + pcol)       = lo0;
                *(uint32_t*)(smem + (psh_base - s0u) + (r0 + 8) * PROWB + pcol) = hi1;
                *(uint32_t*)(smem + (psl_base - s0u) + (r0 + 8) * PROWB + pcol) = lo1;
            }
            se0 += __shfl_xor_sync(0xffffffffu, se0, 1);
            se0 += __shfl_xor_sync(0xffffffffu, se0, 2);
            se1 += __shfl_xor_sync(0xffffffffu, se1, 1);
            se1 += __shfl_xor_sync(0xffffffffu, se1, 2);
            mrow0 = mn0; mrow1 = mn1;
            lrow0 = lrow0 * al0 + se0;
            lrow1 = lrow1 * al1 + se1;
            #pragma unroll
            for (int a = 0; a < 16; ++a) {
                oacc[a][0] *= al0; oacc[a][1] *= al0;
                oacc[a][2] *= al1; oacc[a][3] *= al1;
            }
            __syncwarp();

            // ---- O += P V (bf16x3) ----
            const uint32_t vrow = (uint32_t)((lane & 7) + ((lane >> 3) & 1) * 8);
            const uint32_t vco  = (uint32_t)((lane >> 4) * 16);   // *2B for 8 cols
            #pragma unroll
            for (int ks2 = 0; ks2 < 2; ++ks2) {
                uint32_t ph[4], pl[4];
                uint32_t pa = (uint32_t)((lane & 15) * PROWB + (ks2 * 16 + (lane >> 4) * 8) * 2);
                LDSM4(ph, psh_base + pa);
                LDSM4(pl, psl_base + pa);
                #pragma unroll
                for (int hf = 0; hf < 8; ++hf) {
                    uint32_t bvh[4], bvl[4];
                    uint32_t voff = (ks2 * 16 + vrow) * KROWB + hf * 32 + vco;
                    LDSM4T(bvh, vH + voff);
                    LDSM4T(bvl, vL + voff);
                    MMA16816(oacc[2*hf],     ph, bvh[0], bvh[1]);
                    MMA16816(oacc[2*hf],     pl, bvh[0], bvh[1]);
                    MMA16816(oacc[2*hf],     ph, bvl[0], bvl[1]);
                    MMA16816(oacc[2*hf + 1], ph, bvh[2], bvh[3]);
                    MMA16816(oacc[2*hf + 1], pl, bvh[2], bvh[3]);
                    MMA16816(oacc[2*hf + 1], ph, bvl[2], bvl[3]);
                }
            }
        }
    }

    // ---- epilogue: normalize + split-store enc ----
    float inv0 = 1.0f / lrow0, inv1 = 1.0f / lrow1;
    #pragma unroll
    for (int nt = 0; nt < 16; ++nt) {
        int hcol = nt * 8 + (lane & 3) * 2;
        size_t o0 = ((bT + tw + r0) * NC + n) * HC + hcol;
        size_t o1 = ((bT + tw + r0 + 8) * NC + n) * HC + hcol;
        uint32_t lo0, lo1;
        uint32_t hi0 = pack_split2(oacc[nt][0] * inv0, oacc[nt][1] * inv0, lo0);
        uint32_t hi1 = pack_split2(oacc[nt][2] * inv1, oacc[nt][3] * inv1, lo1);
        *(uint32_t*)((char*)ench + o0 * 2) = hi0;
        *(uint32_t*)((char*)encl + o0 * 2) = lo0;
        *(uint32_t*)((char*)ench + o1 * 2) = hi1;
        *(uint32_t*)((char*)encl + o1 * 2) = lo1;
    }
}

// ---------------- host ----------------
extern "C" void kernel_launch(void* const* d_in, const int* in_sizes, int n_in,
                              void* d_out, int out_size)
{
    (void)in_sizes; (void)n_in; (void)out_size;
    const float* x0  = (const float*)d_in[0];
    const float* x1  = (const float*)d_in[1];
    const int*   pos = (const int*)  d_in[2];
    const float* q0w = (const float*)d_in[4];
    const float* q1w = (const float*)d_in[5];
    const float* k0w = (const float*)d_in[6];
    const float* k1w = (const float*)d_in[7];
    const float* v0w = (const float*)d_in[8];
    const float* v1w = (const float*)d_in[9];
    const float* o0w = (const float*)d_in[10];
    const float* o1w = (const float*)d_in[11];
    const float* gt0 = (const float*)d_in[12];
    const float* gt1 = (const float*)d_in[13];
    const float* up0 = (const float*)d_in[14];
    const float* up1 = (const float*)d_in[15];
    const float* dw0 = (const float*)d_in[16];
    const float* dw1 = (const float*)d_in[17];
    const float* pa0 = (const float*)d_in[18];
    const float* pa1 = (const float*)d_in[19];
    const float* pf0 = (const float*)d_in[20];
    const float* pf1 = (const float*)d_in[21];
    float* out = (float*)d_out;

    float *qb, *kb, *vb, *res, *gate;
    bf16 *preh, *prel, *hidh, *hidl, *ench, *encl, *guh, *gul, *wh, *wl;
    bf16 *qhb, *qlb, *khb, *klb, *vhb, *vlb;
    cudaGetSymbolAddress((void**)&qb,   g_q);
    cudaGetSymbolAddress((void**)&kb,   g_k);
    cudaGetSymbolAddress((void**)&vb,   g_v);
    cudaGetSymbolAddress((void**)&res,  g_res);
    cudaGetSymbolAddress((void**)&gate, g_gate);
    cudaGetSymbolAddress((void**)&preh, g_preh);
    cudaGetSymbolAddress((void**)&prel, g_prel);
    cudaGetSymbolAddress((void**)&hidh, g_hidh);
    cudaGetSymbolAddress((void**)&hidl, g_hidl);
    cudaGetSymbolAddress((void**)&ench, g_ench);
    cudaGetSymbolAddress((void**)&encl, g_encl);
    cudaGetSymbolAddress((void**)&guh,  g_guh);
    cudaGetSymbolAddress((void**)&gul,  g_gul);
    cudaGetSymbolAddress((void**)&wh,   g_wh);
    cudaGetSymbolAddress((void**)&wl,   g_wl);
    cudaGetSymbolAddress((void**)&qhb,  g_qh);
    cudaGetSymbolAddress((void**)&qlb,  g_ql);
    cudaGetSymbolAddress((void**)&khb,  g_kh);
    cudaGetSymbolAddress((void**)&klb,  g_kl);
    cudaGetSymbolAddress((void**)&vhb,  g_vh);
    cudaGetSymbolAddress((void**)&vlb,  g_vl);

    cudaFuncSetAttribute(gemm_tc, cudaFuncAttributeMaxDynamicSharedMemorySize, TC_SMEM_BYTES);
    cudaFuncSetAttribute(attn_mma_kernel, cudaFuncAttributeMaxDynamicSharedMemorySize, ATT_SMEM);

    const size_t QN = (size_t)NHC * DC;
    const size_t KN = (size_t)KHC * DC;
    const size_t FN = (size_t)FC * DC;
    const size_t oq0 = 0,         oq1 = oq0 + QN;
    const size_t ok0 = oq1 + QN,  ok1 = ok0 + KN;
    const size_t ov0 = ok1 + KN,  ov1 = ov0 + KN;
    const size_t oo0 = ov1 + KN,  oo1 = oo0 + QN;
    const size_t og0 = oo1 + QN,  og1 = og0 + FN;
    const size_t ou0 = og1 + FN,  ou1 = ou0 + FN;
    const size_t od0 = ou1 + FN,  od1 = od0 + FN;

    // 0. weight fp32 -> bf16 hi/lo
    cvt_split_kernel<<<(int)(QN / 2048), 256>>>(q0w, wh + oq0, wl + oq0, (int)QN);
    cvt_split_kernel<<<(int)(QN / 2048), 256>>>(q1w, wh + oq1, wl + oq1, (int)QN);
    cvt_split_kernel<<<(int)(KN / 2048), 256>>>(k0w, wh + ok0, wl + ok0, (int)KN);
    cvt_split_kernel<<<(int)(KN / 2048), 256>>>(k1w, wh + ok1, wl + ok1, (int)KN);
    cvt_split_kernel<<<(int)(KN / 2048), 256>>>(v0w, wh + ov0, wl + ov0, (int)KN);
    cvt_split_kernel<<<(int)(KN / 2048), 256>>>(v1w, wh + ov1, wl + ov1, (int)KN);
    cvt_split_kernel<<<(int)(QN / 2048), 256>>>(o0w, wh + oo0, wl + oo0, (int)QN);
    cvt_split_kernel<<<(int)(QN / 2048), 256>>>(o1w, wh + oo1, wl + oo1, (int)QN);
    cvt_split_kernel<<<(int)(FN / 2048), 256>>>(gt0, wh + og0, wl + og0, (int)FN);
    cvt_split_kernel<<<(int)(FN / 2048), 256>>>(gt1, wh + og1, wl + og1, (int)FN);
    cvt_split_kernel<<<(int)(FN / 2048), 256>>>(up0, wh + ou0, wl + ou0, (int)FN);
    cvt_split_kernel<<<(int)(FN / 2048), 256>>>(up1, wh + ou1, wl + ou1, (int)FN);
    cvt_split_kernel<<<(int)(FN / 2048), 256>>>(dw0, wh + od0, wl + od0, (int)FN);
    cvt_split_kernel<<<(int)(FN / 2048), 256>>>(dw1, wh + od1, wl + od1, (int)FN);

    // 1. pre-attn rmsnorm -> bf16 hi/lo
    rmsnorm_kernel<<<BB * T0C, 256>>>(x0, preh, prel, pa0, 0, 0);
    rmsnorm_kernel<<<BB * T0C, 256>>>(x1, preh, prel, pa1, 1, 0);

    // 2. QKV projections
    {
        dim3 gq(NHC / 128, T0C / 128, 4);
        gemm_tc<<<gq, 256, TC_SMEM_BYTES>>>(preh, prel, wh + oq0, wl + oq0, wh + oq1, wl + oq1,
                                            qb, DC, NHC, 0, 0, 0, 0, 0, 0, 0, 0);
        dim3 gk(KHC / 128, T0C / 128, 4);
        gemm_tc<<<gk, 256, TC_SMEM_BYTES>>>(preh, prel, wh + ok0, wl + ok0, wh + ok1, wl + ok1,
                                            kb, DC, KHC, 0, 0, 0, 0, 0, 0, 0, 0);
        gemm_tc<<<gk, 256, TC_SMEM_BYTES>>>(preh, prel, wh + ov0, wl + ov0, wh + ov1, wl + ov1,
                                            vb, DC, KHC, 0, 0, 0, 0, 0, 0, 0, 0);
    }

    // 3. RoPE + scale + split to bf16 hi/lo
    rope_split_kernel<<<BB * TOTC, 256>>>(qb, kb, vb, pos, qhb, qlb, khb, klb, vhb, vlb);

    // 4. attention (mma.sync flash) -> writes ench/encl directly
    {
        dim3 ga(TOTC / ATT_BM, NC, BB);
        attn_mma_kernel<<<ga, 256, ATT_SMEM>>>(qhb, qlb, khb, klb, vhb, vlb, ench, encl);
    }

    // 5. O projection + residual
    {
        dim3 go(DC / 128, T0C / 128, 4);
        gemm_tc<<<go, 256, TC_SMEM_BYTES>>>(ench, encl, wh + oo0, wl + oo0, wh + oo1, wl + oo1,
                                            res, NHC, DC, 2, x0, x1, 0, 0, 0, 0, 0);
    }

    // 6. pre-ffw rmsnorm -> bf16 hi/lo
    rmsnorm_kernel<<<BB * T0C, 256>>>(res, hidh, hidl, pf0, 0, 1);
    rmsnorm_kernel<<<BB * T0C, 256>>>(res, hidh, hidl, pf1, 1, 1);

    // 7. gate (gelu) then up (fused gelu(gate)*up split) projections
    {
        dim3 gf(FC / 128, T0C / 128, 4);
        gemm_tc<<<gf, 256, TC_SMEM_BYTES>>>(hidh, hidl, wh + og0, wl + og0, wh + og1, wl + og1,
                                            gate, DC, FC, 1, 0, 0, 0, 0, 0, 0, 0);
        gemm_tc<<<gf, 256, TC_SMEM_BYTES>>>(hidh, hidl, wh + ou0, wl + ou0, wh + ou1, wl + ou1,
                                            gate, DC, FC, 3, 0, 0, 0, 0, gate, guh, gul);
    }

    // 8. down projection + residual -> out (stream-major)
    {
        dim3 gd(DC / 128, T0C / 128, 4);
        gemm_tc<<<gd, 256, TC_SMEM_BYTES>>>(guh, gul, wh + od0, wl + od0, wh + od1, wl + od1,
                                            out, FC, DC, 2, res, 0, 1, 1, 0, 0, 0);
    }
}

// round 5
// speedup vs baseline: 3.6354x; 1.1412x over previous
#include <cuda_runtime.h>
#include <cuda_bf16.h>
#include <math.h>
#include <float.h>
#include <stdint.h>

// ---------------- problem constants ----------------
#define BB   2
#define T0C  1024
#define TOTC 2048
#define DC   2048
#define NC   16
#define KC   8
#define HC   128
#define FC   8192
#define NHC  2048   // N*H
#define KHC  1024   // K*H
#define GC   2      // N/K

typedef __nv_bfloat16 bf16;

// ---------------- helpers ----------------
__device__ __forceinline__ uint32_t smem_to_u32(const void* p) {
    uint32_t a;
    asm("{ .reg .u64 t; cvta.to.shared.u64 t, %1; cvt.u32.u64 %0, t; }" : "=r"(a) : "l"(p));
    return a;
}
#define LDSM4(r, addr) \
    asm volatile("ldmatrix.sync.aligned.m8n8.x4.shared.b16 {%0,%1,%2,%3}, [%4];" \
        : "=r"((r)[0]), "=r"((r)[1]), "=r"((r)[2]), "=r"((r)[3]) : "r"(addr))
#define LDSM4T(r, addr) \
    asm volatile("ldmatrix.sync.aligned.m8n8.x4.trans.shared.b16 {%0,%1,%2,%3}, [%4];" \
        : "=r"((r)[0]), "=r"((r)[1]), "=r"((r)[2]), "=r"((r)[3]) : "r"(addr))
#define MMA16816(d, a, b0, b1) \
    asm volatile("mma.sync.aligned.m16n8k16.row.col.f32.bf16.bf16.f32 " \
        "{%0,%1,%2,%3},{%4,%5,%6,%7},{%8,%9},{%0,%1,%2,%3};" \
        : "+f"((d)[0]), "+f"((d)[1]), "+f"((d)[2]), "+f"((d)[3]) \
        : "r"((a)[0]), "r"((a)[1]), "r"((a)[2]), "r"((a)[3]), "r"(b0), "r"(b1))
#define CP_ASYNC16(saddr, gaddr) \
    asm volatile("cp.async.cg.shared.global [%0], [%1], 16;" :: "r"(saddr), "l"(gaddr))
#define CP_COMMIT() asm volatile("cp.async.commit_group;" ::: "memory")
#define CP_WAIT(n)  asm volatile("cp.async.wait_group %0;" :: "n"(n) : "memory")

// ---------------- scratch (device globals; no runtime alloc) ----------------
__device__ float g_qkv [(size_t)BB*TOTC*4096];   // packed q(2048)|k(1024)|v(1024)
__device__ float g_res [(size_t)BB*TOTC*DC];
__device__ float g_gate[(size_t)BB*TOTC*FC];

__device__ bf16 g_preh[(size_t)BB*TOTC*DC];
__device__ bf16 g_prel[(size_t)BB*TOTC*DC];
__device__ bf16 g_hidh[(size_t)BB*TOTC*DC];
__device__ bf16 g_hidl[(size_t)BB*TOTC*DC];
__device__ bf16 g_ench[(size_t)BB*TOTC*NHC];
__device__ bf16 g_encl[(size_t)BB*TOTC*NHC];
__device__ bf16 g_guh [(size_t)BB*TOTC*FC];
__device__ bf16 g_gul [(size_t)BB*TOTC*FC];
__device__ bf16 g_qh  [(size_t)BB*TOTC*NHC];
__device__ bf16 g_ql  [(size_t)BB*TOTC*NHC];
__device__ bf16 g_kh  [(size_t)BB*TOTC*KHC];
__device__ bf16 g_kl  [(size_t)BB*TOTC*KHC];
__device__ bf16 g_vh  [(size_t)BB*TOTC*KHC];
__device__ bf16 g_vl  [(size_t)BB*TOTC*KHC];
__device__ bf16 g_wh  [125829120];
__device__ bf16 g_wl  [125829120];

// ---------------- elementwise helpers ----------------
__device__ __forceinline__ float gelu_tanh(float x) {
    float x3 = x * x * x;
    return 0.5f * x * (1.0f + tanhf(0.7978845608028654f * (x + 0.044715f * x3)));
}
__device__ __forceinline__ void split_store(float v, bf16* h, bf16* l) {
    bf16 hh = __float2bfloat16(v);
    *h = hh;
    *l = __float2bfloat16(v - __bfloat162float(hh));
}
__device__ __forceinline__ uint32_t pack_split2(float a, float b, uint32_t& lo) {
    bf16 ha = __float2bfloat16(a), hb = __float2bfloat16(b);
    bf16 la = __float2bfloat16(a - __bfloat162float(ha));
    bf16 lb = __float2bfloat16(b - __bfloat162float(hb));
    lo = (uint32_t)__bfloat16_as_ushort(la) | ((uint32_t)__bfloat16_as_ushort(lb) << 16);
    return (uint32_t)__bfloat16_as_ushort(ha) | ((uint32_t)__bfloat16_as_ushort(hb) << 16);
}

// fp32 -> bf16 hi/lo split, 8 elems/thread, vectorized 16B stores
__global__ void cvt_split_kernel(const float* __restrict__ src,
                                 bf16* __restrict__ h, bf16* __restrict__ l, int n)
{
    int i = (blockIdx.x * 256 + threadIdx.x) * 8;
    if (i >= n) return;
    float4 a = *(const float4*)(src + i);
    float4 b = *(const float4*)(src + i + 4);
    uint4 hv, lv;
    hv.x = pack_split2(a.x, a.y, lv.x);
    hv.y = pack_split2(a.z, a.w, lv.y);
    hv.z = pack_split2(b.x, b.y, lv.z);
    hv.w = pack_split2(b.z, b.w, lv.w);
    *(uint4*)(h + i) = hv;
    *(uint4*)(l + i) = lv;
}

// ---------------- rmsnorm (writes bf16 hi/lo split) ----------------
__global__ void rmsnorm_kernel(const float* __restrict__ src,
                               bf16* __restrict__ dsth, bf16* __restrict__ dstl,
                               const float* __restrict__ scale, int istream, int srcmode)
{
    int row = blockIdx.x;               // 0 .. B*T0-1
    int b = row / T0C, t = row % T0C;
    size_t crow = (size_t)b * TOTC + (size_t)istream * T0C + t;
    const float* s = src + (srcmode ? crow : (size_t)row) * DC;
    bf16* oh = dsth + crow * DC;
    bf16* ol = dstl + crow * DC;

    __shared__ float red[256];
    float ss = 0.f;
    for (int d = threadIdx.x; d < DC; d += 256) { float v = s[d]; ss += v * v; }
    red[threadIdx.x] = ss;
    __syncthreads();
    for (int st = 128; st > 0; st >>= 1) {
        if (threadIdx.x < st) red[threadIdx.x] += red[threadIdx.x + st];
        __syncthreads();
    }
    float inv = rsqrtf(red[0] * (1.0f / DC) + 1e-6f);
    for (int d = threadIdx.x; d < DC; d += 256) {
        float v = s[d] * inv * (1.0f + scale[d]);
        split_store(v, oh + d, ol + d);
    }
}

// ---------------- rope + split (reads packed qkv; q,k roped+split; v split) ----------------
__global__ void rope_split_kernel(const float* __restrict__ qkv, const int* __restrict__ positions,
                                  bf16* __restrict__ qh, bf16* __restrict__ ql,
                                  bf16* __restrict__ kh, bf16* __restrict__ kl,
                                  bf16* __restrict__ vh, bf16* __restrict__ vl)
{
    int row = blockIdx.x;                       // b*TOT + t
    float pos = (float)positions[row];
    const float QSCALE = 0.08838834764831845f;  // 128^-0.5
    const float* src = qkv + (size_t)row * 4096;
    for (int w = threadIdx.x; w < (NC + KC) * 64; w += 256) {
        int head = w >> 6;
        int j = w & 63;
        float ts = powf(10000.0f, (float)j * (1.0f / 64.0f));
        float sn, cs;
        sincosf(pos / ts, &sn, &cs);
        if (head < NC) {
            float x1 = src[head * HC + j], x2 = src[head * HC + j + 64];
            size_t o = ((size_t)row * NC + head) * HC;
            split_store((x1 * cs - x2 * sn) * QSCALE, qh + o + j, ql + o + j);
            split_store((x2 * cs + x1 * sn) * QSCALE, qh + o + j + 64, ql + o + j + 64);
        } else {
            int kkh = head - NC;
            float x1 = src[2048 + kkh * HC + j], x2 = src[2048 + kkh * HC + j + 64];
            size_t o = ((size_t)row * KC + kkh) * HC;
            split_store(x1 * cs - x2 * sn, kh + o + j, kl + o + j);
            split_store(x2 * cs + x1 * sn, kh + o + j + 64, kl + o + j + 64);
        }
    }
    for (int idx = threadIdx.x; idx < KHC; idx += 256) {
        size_t o = (size_t)row * KHC + idx;
        split_store(src[3072 + idx], vh + o, vl + o);
    }
}

// ---------------- mma.sync GEMM: C = A @ W^T (+epilogue), bf16x3 split ----------------
// CTA 128x256, warp tile 64x64, GBK=32, 3-stage cp.async pipeline.
// epi: 0 none, 1 gelu, 2 +residual, 3 gelu-gate-mul-split (reads G fp32, writes GH/GL bf16)
#define GBM 128
#define GBN 256
#define GBK 32
#define GSTAGES 3
#define ROWB   80
#define TILEA_B (128 * ROWB)                 // 10240
#define TILEW_B (256 * ROWB)                 // 20480
#define STAGE_B (2 * TILEA_B + 2 * TILEW_B)  // 61440
#define TC_SMEM_BYTES (GSTAGES * STAGE_B)    // 184320

__global__ __launch_bounds__(256, 1)
void gemm_tc(const bf16* __restrict__ Ah_, const bf16* __restrict__ Al_,
             const bf16* __restrict__ W0h, const bf16* __restrict__ W0l,
             const bf16* __restrict__ W1h, const bf16* __restrict__ W1l,
             float* __restrict__ C_, int Kd, int Nout, int epi,
             const float* __restrict__ R0, const float* __restrict__ R1,
             int resmode, int outmode,
             const float* __restrict__ G_, bf16* __restrict__ GH_, bf16* __restrict__ GL_)
{
    extern __shared__ char smem[];
    const uint32_t s0 = smem_to_u32(smem);

    const int tid = threadIdx.x;
    const int lane = tid & 31, warp = tid >> 5;
    const int wm = warp >> 2, wn = warp & 3;      // warp tile: 64 (m) x 64 (n)

    const int z = blockIdx.z, i = z >> 1, b = z & 1;
    const size_t arow0 = (size_t)b * TOTC + (size_t)i * T0C;
    const bf16* Ah = Ah_ + arow0 * Kd;
    const bf16* Al = Al_ + arow0 * Kd;
    const bf16* Wh = i ? W1h : W0h;
    const bf16* Wl = i ? W1l : W0l;
    float* C = (outmode == 0) ? (C_ + arow0 * (size_t)Nout)
                              : (C_ + ((size_t)i * BB * T0C + (size_t)b * T0C) * (size_t)Nout);
    const float* R = 0;
    if (epi == 2) R = (resmode == 0) ? ((i ? R1 : R0) + (size_t)b * T0C * Nout)
                                     : (R0 + arow0 * (size_t)Nout);
    const float* G = 0; bf16* GH = 0; bf16* GL = 0;
    if (epi == 3) { G = G_ + arow0 * (size_t)Nout; GH = GH_ + arow0 * (size_t)Nout; GL = GL_ + arow0 * (size_t)Nout; }

    const int m0 = blockIdx.y * GBM, n0 = blockIdx.x * GBN;
    const int nk = Kd / GBK;

    #define ISSUE_STAGE(cc) do {                                                 \
        int kk0 = (cc) * GBK;                                                    \
        uint32_t sbase = s0 + ((cc) % GSTAGES) * STAGE_B;                        \
        _Pragma("unroll")                                                        \
        for (int it = 0; it < 12; ++it) {                                        \
            int idx = tid + it * 256;                                            \
            const bf16* gp; uint32_t sa;                                         \
            if (idx < 1024) {                                                    \
                int tt = idx >> 9;                                               \
                int cid = idx & 511;                                             \
                int row = cid >> 2, ch = cid & 3;                                \
                sa = sbase + tt * TILEA_B + row * ROWB + ch * 16;                \
                gp = (tt ? Al : Ah) + (size_t)(m0 + row) * Kd + kk0 + ch * 8;    \
            } else {                                                             \
                int cid = idx - 1024;                                            \
                int tt = cid >> 10;                                              \
                cid &= 1023;                                                     \
                int row = cid >> 2, ch = cid & 3;                                \
                sa = sbase + 2 * TILEA_B + tt * TILEW_B + row * ROWB + ch * 16;  \
                gp = (tt ? Wl : Wh) + (size_t)(n0 + row) * Kd + kk0 + ch * 8;    \
            }                                                                    \
            CP_ASYNC16(sa, gp);                                                  \
        }                                                                        \
        CP_COMMIT();                                                             \
    } while (0)

    float acc[4][8][4];
    #pragma unroll
    for (int mf = 0; mf < 4; ++mf)
        #pragma unroll
        for (int nf = 0; nf < 8; ++nf)
            #pragma unroll
            for (int r = 0; r < 4; ++r) acc[mf][nf][r] = 0.f;

    const int a_row = wm * 64 + (lane & 15);
    const int a_cj  = lane >> 4;
    const int b_row = wn * 64 + (lane & 7) + ((lane >> 4) & 1) * 8;
    const int b_cj  = (lane >> 3) & 1;

    ISSUE_STAGE(0);
    ISSUE_STAGE(1);

    for (int c = 0; c < nk; ++c) {
        if (c + 2 < nk) { ISSUE_STAGE(c + 2); CP_WAIT(2); }
        else if (c + 1 < nk) CP_WAIT(1);
        else CP_WAIT(0);
        __syncthreads();

        uint32_t sbase = s0 + (c % GSTAGES) * STAGE_B;
        uint32_t aH = sbase, aL = sbase + TILEA_B;
        uint32_t bH = sbase + 2 * TILEA_B, bL = bH + TILEW_B;

        #pragma unroll
        for (int ks = 0; ks < 2; ++ks) {
            uint32_t ah[4][4], al[4][4];
            uint32_t aoff = (uint32_t)(a_row * ROWB + (ks * 2 + a_cj) * 16);
            #pragma unroll
            for (int mf = 0; mf < 4; ++mf) {
                LDSM4(ah[mf], aH + aoff + mf * (16 * ROWB));
                LDSM4(al[mf], aL + aoff + mf * (16 * ROWB));
            }
            uint32_t boff = (uint32_t)(b_row * ROWB + (ks * 2 + b_cj) * 16);
            #pragma unroll
            for (int nf2 = 0; nf2 < 4; ++nf2) {
                uint32_t bh[4], bl[4];
                LDSM4(bh, bH + boff + nf2 * (16 * ROWB));
                LDSM4(bl, bL + boff + nf2 * (16 * ROWB));
                #pragma unroll
                for (int mf = 0; mf < 4; ++mf) {
                    MMA16816(acc[mf][nf2 * 2], ah[mf], bh[0], bh[1]);
                    MMA16816(acc[mf][nf2 * 2], al[mf], bh[0], bh[1]);
                    MMA16816(acc[mf][nf2 * 2], ah[mf], bl[0], bl[1]);
                    MMA16816(acc[mf][nf2 * 2 + 1], ah[mf], bh[2], bh[3]);
                    MMA16816(acc[mf][nf2 * 2 + 1], al[mf], bh[2], bh[3]);
                    MMA16816(acc[mf][nf2 * 2 + 1], ah[mf], bl[2], bl[3]);
                }
            }
        }
        __syncthreads();
    }

    // epilogue
    #pragma unroll
    for (int mf = 0; mf < 4; ++mf) {
        int r0 = m0 + wm * 64 + mf * 16 + (lane >> 2);
        #pragma unroll
        for (int nf = 0; nf < 8; ++nf) {
            int col = n0 + wn * 64 + nf * 8 + (lane & 3) * 2;
            float2 v0 = make_float2(acc[mf][nf][0], acc[mf][nf][1]);
            float2 v1 = make_float2(acc[mf][nf][2], acc[mf][nf][3]);
            if (epi == 3) {
                float2 g0 = *(const float2*)(G + (size_t)r0 * Nout + col);
                float2 g1 = *(const float2*)(G + (size_t)(r0 + 8) * Nout + col);
                uint32_t lo0, lo1;
                uint32_t hi0 = pack_split2(v0.x * g0.x, v0.y * g0.y, lo0);
                uint32_t hi1 = pack_split2(v1.x * g1.x, v1.y * g1.y, lo1);
                *(uint32_t*)((char*)GH + ((size_t)r0 * Nout + col) * 2)       = hi0;
                *(uint32_t*)((char*)GL + ((size_t)r0 * Nout + col) * 2)       = lo0;
                *(uint32_t*)((char*)GH + ((size_t)(r0 + 8) * Nout + col) * 2) = hi1;
                *(uint32_t*)((char*)GL + ((size_t)(r0 + 8) * Nout + col) * 2) = lo1;
            } else {
                if (epi == 1) {
                    v0.x = gelu_tanh(v0.x); v0.y = gelu_tanh(v0.y);
                    v1.x = gelu_tanh(v1.x); v1.y = gelu_tanh(v1.y);
                } else if (epi == 2) {
                    float2 r4a = *(const float2*)(R + (size_t)r0 * Nout + col);
                    float2 r4b = *(const float2*)(R + (size_t)(r0 + 8) * Nout + col);
                    v0.x += r4a.x; v0.y += r4a.y;
                    v1.x += r4b.x; v1.y += r4b.y;
                }
                *(float2*)(C + (size_t)r0 * Nout + col)       = v0;
                *(float2*)(C + (size_t)(r0 + 8) * Nout + col) = v1;
            }
        }
    }
}

// ---------------- attention: mma.sync flash kernel, bf16 hi/lo splits ----------------
#define ATT_BM 128
#define ATT_BN 32
#define QROWB 272
#define KROWB 272
#define PROWB 80
#define SQH 0
#define SQL 34816
#define SKV 69632
#define KVTILE 8704
#define SPH 139264
#define SPL 149504
#define ATT_SMEM 159744
#define NEGA (-1e30f)

__global__ __launch_bounds__(256, 1)
void attn_mma_kernel(const bf16* __restrict__ qh, const bf16* __restrict__ ql,
                     const bf16* __restrict__ kh, const bf16* __restrict__ kl,
                     const bf16* __restrict__ vh, const bf16* __restrict__ vl,
                     bf16* __restrict__ ench, bf16* __restrict__ encl)
{
    extern __shared__ char smem[];
    const uint32_t s0u = smem_to_u32(smem);
    const int tid = threadIdx.x, lane = tid & 31, w = tid >> 5;
    const int bq = blockIdx.z;
    const int n = blockIdx.y;
    const int kk = n >> 1;
    const int t0 = ((int)gridDim.x - 1 - (int)blockIdx.x) * ATT_BM;   // big CTAs first
    const size_t bT = (size_t)bq * TOTC;

    // Q tile hi/lo -> smem
    #pragma unroll
    for (int it = 0; it < 16; ++it) {
        int idx = tid + it * 256;
        int tens = idx >> 11, row = (idx >> 4) & 127, ch = idx & 15;
        const bf16* src = (tens ? ql : qh) + ((bT + t0 + row) * NC + n) * HC + ch * 8;
        CP_ASYNC16(s0u + (tens ? SQL : SQH) + row * QROWB + ch * 16, src);
    }
    CP_COMMIT();

    #define LOAD_KV(j) do {                                                        \
        int _bf = (j) & 1; int _s0 = (j) * ATT_BN;                                 \
        _Pragma("unroll")                                                          \
        for (int it = 0; it < 8; ++it) {                                           \
            int idx = tid + it * 256;                                              \
            int tt = idx >> 9, cid = idx & 511, row = cid >> 4, ch = cid & 15;     \
            const bf16* srcp;                                                      \
            if (tt == 0) srcp = kh; else if (tt == 1) srcp = kl;                   \
            else if (tt == 2) srcp = vh; else srcp = vl;                           \
            srcp += ((bT + _s0 + row) * KC + kk) * HC + ch * 8;                    \
            CP_ASYNC16(s0u + SKV + (_bf * 4 + tt) * KVTILE + row * KROWB + ch * 16, srcp); \
        }                                                                          \
        CP_COMMIT();                                                               \
    } while (0)

    const int nb = t0 / ATT_BN + 4;
    LOAD_KV(0);

    const int tw = t0 + w * 16;
    const int r0 = lane >> 2;                 // warp-local rows r0, r0+8
    float oacc[16][4];
    #pragma unroll
    for (int a = 0; a < 16; ++a) { oacc[a][0] = oacc[a][1] = oacc[a][2] = oacc[a][3] = 0.f; }
    float mrow0 = NEGA, mrow1 = NEGA, lrow0 = 0.f, lrow1 = 0.f;

    const uint32_t psh_base = s0u + SPH + (w * 16) * PROWB;
    const uint32_t psl_base = s0u + SPL + (w * 16) * PROWB;

    for (int j = 0; j < nb; ++j) {
        CP_WAIT(0);
        __syncthreads();
        if (j + 1 < nb) LOAD_KV(j + 1);

        const int sblk = j * ATT_BN;
        const int bf = j & 1;
        const uint32_t kH = s0u + SKV + (bf * 4 + 0) * KVTILE;
        const uint32_t kL = s0u + SKV + (bf * 4 + 1) * KVTILE;
        const uint32_t vH = s0u + SKV + (bf * 4 + 2) * KVTILE;
        const uint32_t vL = s0u + SKV + (bf * 4 + 3) * KVTILE;

        if (sblk <= tw + 15) {                 // warp has unmasked rows
            // ---- S = Q K^T (bf16x3) ----
            float sacc[4][4];
            #pragma unroll
            for (int nf = 0; nf < 4; ++nf) { sacc[nf][0]=sacc[nf][1]=sacc[nf][2]=sacc[nf][3]=0.f; }
            const uint32_t aoff_base = (uint32_t)((w * 16 + (lane & 15)) * QROWB + (lane >> 4) * 16);
            const uint32_t brow = (uint32_t)((lane & 7) + ((lane >> 4) & 1) * 8);
            const uint32_t bco  = (uint32_t)(((lane >> 3) & 1) * 16);
            #pragma unroll
            for (int ks = 0; ks < 8; ++ks) {
                uint32_t ah[4], al[4], bh0[4], bh1[4], bl0[4], bl1[4];
                uint32_t aoff = aoff_base + ks * 32;
                LDSM4(ah, s0u + SQH + aoff);
                LDSM4(al, s0u + SQL + aoff);
                uint32_t boff0 = brow * KROWB + ks * 32 + bco;
                uint32_t boff1 = boff0 + 16 * KROWB;
                LDSM4(bh0, kH + boff0); LDSM4(bh1, kH + boff1);
                LDSM4(bl0, kL + boff0); LDSM4(bl1, kL + boff1);
                MMA16816(sacc[0], ah, bh0[0], bh0[1]);
                MMA16816(sacc[0], al, bh0[0], bh0[1]);
                MMA16816(sacc[0], ah, bl0[0], bl0[1]);
                MMA16816(sacc[1], ah, bh0[2], bh0[3]);
                MMA16816(sacc[1], al, bh0[2], bh0[3]);
                MMA16816(sacc[1], ah, bl0[2], bl0[3]);
                MMA16816(sacc[2], ah, bh1[0], bh1[1]);
                MMA16816(sacc[2], al, bh1[0], bh1[1]);
                MMA16816(sacc[2], ah, bl1[0], bl1[1]);
                MMA16816(sacc[3], ah, bh1[2], bh1[3]);
                MMA16816(sacc[3], al, bh1[2], bh1[3]);
                MMA16816(sacc[3], ah, bl1[2], bl1[3]);
            }

            // ---- causal mask (diagonal blocks only) ----
            if (sblk + ATT_BN - 1 > tw) {
                #pragma unroll
                for (int nf = 0; nf < 4; ++nf) {
                    int sg = sblk + nf * 8 + (lane & 3) * 2;
                    int tg0 = tw + r0, tg1 = tg0 + 8;
                    if (sg     > tg0) sacc[nf][0] = NEGA;
                    if (sg + 1 > tg0) sacc[nf][1] = NEGA;
                    if (sg     > tg1) sacc[nf][2] = NEGA;
                    if (sg + 1 > tg1) sacc[nf][3] = NEGA;
                }
            }

            // ---- online softmax ----
            float mx0 = NEGA, mx1 = NEGA;
            #pragma unroll
            for (int nf = 0; nf < 4; ++nf) {
                mx0 = fmaxf(mx0, fmaxf(sacc[nf][0], sacc[nf][1]));
                mx1 = fmaxf(mx1, fmaxf(sacc[nf][2], sacc[nf][3]));
            }
            mx0 = fmaxf(mx0, __shfl_xor_sync(0xffffffffu, mx0, 1));
            mx0 = fmaxf(mx0, __shfl_xor_sync(0xffffffffu, mx0, 2));
            mx1 = fmaxf(mx1, __shfl_xor_sync(0xffffffffu, mx1, 1));
            mx1 = fmaxf(mx1, __shfl_xor_sync(0xffffffffu, mx1, 2));
            float mn0 = fmaxf(mrow0, mx0), mn1 = fmaxf(mrow1, mx1);
            float al0 = __expf(mrow0 - mn0), al1 = __expf(mrow1 - mn1);
            float se0 = 0.f, se1 = 0.f;
            #pragma unroll
            for (int nf = 0; nf < 4; ++nf) {
                float p0 = __expf(sacc[nf][0] - mn0);
                float p1 = __expf(sacc[nf][1] - mn0);
                float p2 = __expf(sacc[nf][2] - mn1);
                float p3 = __expf(sacc[nf][3] - mn1);
                se0 += p0 + p1; se1 += p2 + p3;
                uint32_t pcol = (uint32_t)((nf * 8 + (lane & 3) * 2) * 2);
                uint32_t lo0, lo1;
                uint32_t hi0 = pack_split2(p0, p1, lo0);
                uint32_t hi1 = pack_split2(p2, p3, lo1);
                *(uint32_t*)(smem + (psh_base - s0u) + r0 * PROWB + pcol)       = hi0;
                *(uint32_t*)(smem + (psl_base - s0u) + r0 * PROWB + pcol)       = lo0;
                *(uint32_t*)(smem + (psh_base - s0u) + (r0 + 8) * PROWB + pcol) = hi1;
                *(uint32_t*)(smem + (psl_base - s0u) + (r0 + 8) * PROWB + pcol) = lo1;
            }
            se0 += __shfl_xor_sync(0xffffffffu, se0, 1);
            se0 += __shfl_xor_sync(0xffffffffu, se0, 2);
            se1 += __shfl_xor_sync(0xffffffffu, se1, 1);
            se1 += __shfl_xor_sync(0xffffffffu, se1, 2);
            mrow0 = mn0; mrow1 = mn1;
            lrow0 = lrow0 * al0 + se0;
            lrow1 = lrow1 * al1 + se1;
            #pragma unroll
            for (int a = 0; a < 16; ++a) {
                oacc[a][0] *= al0; oacc[a][1] *= al0;
                oacc[a][2] *= al1; oacc[a][3] *= al1;
            }
            __syncwarp();

            // ---- O += P V (bf16x3) ----
            const uint32_t vrow = (uint32_t)((lane & 7) + ((lane >> 3) & 1) * 8);
            const uint32_t vco  = (uint32_t)((lane >> 4) * 16);
            #pragma unroll
            for (int ks2 = 0; ks2 < 2; ++ks2) {
                uint32_t ph[4], pl[4];
                uint32_t pa = (uint32_t)((lane & 15) * PROWB + (ks2 * 16 + (lane >> 4) * 8) * 2);
                LDSM4(ph, psh_base + pa);
                LDSM4(pl, psl_base + pa);
                #pragma unroll
                for (int hf = 0; hf < 8; ++hf) {
                    uint32_t bvh[4], bvl[4];
                    uint32_t voff = (ks2 * 16 + vrow) * KROWB + hf * 32 + vco;
                    LDSM4T(bvh, vH + voff);
                    LDSM4T(bvl, vL + voff);
                    MMA16816(oacc[2*hf],     ph, bvh[0], bvh[1]);
                    MMA16816(oacc[2*hf],     pl, bvh[0], bvh[1]);
                    MMA16816(oacc[2*hf],     ph, bvl[0], bvl[1]);
                    MMA16816(oacc[2*hf + 1], ph, bvh[2], bvh[3]);
                    MMA16816(oacc[2*hf + 1], pl, bvh[2], bvh[3]);
                    MMA16816(oacc[2*hf + 1], ph, bvl[2], bvl[3]);
                }
            }
        }
    }

    // ---- epilogue: normalize + split-store enc ----
    float inv0 = 1.0f / lrow0, inv1 = 1.0f / lrow1;
    #pragma unroll
    for (int nt = 0; nt < 16; ++nt) {
        int hcol = nt * 8 + (lane & 3) * 2;
        size_t o0 = ((bT + tw + r0) * NC + n) * HC + hcol;
        size_t o1 = ((bT + tw + r0 + 8) * NC + n) * HC + hcol;
        uint32_t lo0, lo1;
        uint32_t hi0 = pack_split2(oacc[nt][0] * inv0, oacc[nt][1] * inv0, lo0);
        uint32_t hi1 = pack_split2(oacc[nt][2] * inv1, oacc[nt][3] * inv1, lo1);
        *(uint32_t*)((char*)ench + o0 * 2) = hi0;
        *(uint32_t*)((char*)encl + o0 * 2) = lo0;
        *(uint32_t*)((char*)ench + o1 * 2) = hi1;
        *(uint32_t*)((char*)encl + o1 * 2) = lo1;
    }
}

// ---------------- host ----------------
extern "C" void kernel_launch(void* const* d_in, const int* in_sizes, int n_in,
                              void* d_out, int out_size)
{
    (void)in_sizes; (void)n_in; (void)out_size;
    const float* x0  = (const float*)d_in[0];
    const float* x1  = (const float*)d_in[1];
    const int*   pos = (const int*)  d_in[2];
    const float* q0w = (const float*)d_in[4];
    const float* q1w = (const float*)d_in[5];
    const float* k0w = (const float*)d_in[6];
    const float* k1w = (const float*)d_in[7];
    const float* v0w = (const float*)d_in[8];
    const float* v1w = (const float*)d_in[9];
    const float* o0w = (const float*)d_in[10];
    const float* o1w = (const float*)d_in[11];
    const float* gt0 = (const float*)d_in[12];
    const float* gt1 = (const float*)d_in[13];
    const float* up0 = (const float*)d_in[14];
    const float* up1 = (const float*)d_in[15];
    const float* dw0 = (const float*)d_in[16];
    const float* dw1 = (const float*)d_in[17];
    const float* pa0 = (const float*)d_in[18];
    const float* pa1 = (const float*)d_in[19];
    const float* pf0 = (const float*)d_in[20];
    const float* pf1 = (const float*)d_in[21];
    float* out = (float*)d_out;

    float *qkv, *res, *gate;
    bf16 *preh, *prel, *hidh, *hidl, *ench, *encl, *guh, *gul, *wh, *wl;
    bf16 *qhb, *qlb, *khb, *klb, *vhb, *vlb;
    cudaGetSymbolAddress((void**)&qkv,  g_qkv);
    cudaGetSymbolAddress((void**)&res,  g_res);
    cudaGetSymbolAddress((void**)&gate, g_gate);
    cudaGetSymbolAddress((void**)&preh, g_preh);
    cudaGetSymbolAddress((void**)&prel, g_prel);
    cudaGetSymbolAddress((void**)&hidh, g_hidh);
    cudaGetSymbolAddress((void**)&hidl, g_hidl);
    cudaGetSymbolAddress((void**)&ench, g_ench);
    cudaGetSymbolAddress((void**)&encl, g_encl);
    cudaGetSymbolAddress((void**)&guh,  g_guh);
    cudaGetSymbolAddress((void**)&gul,  g_gul);
    cudaGetSymbolAddress((void**)&wh,   g_wh);
    cudaGetSymbolAddress((void**)&wl,   g_wl);
    cudaGetSymbolAddress((void**)&qhb,  g_qh);
    cudaGetSymbolAddress((void**)&qlb,  g_ql);
    cudaGetSymbolAddress((void**)&khb,  g_kh);
    cudaGetSymbolAddress((void**)&klb,  g_kl);
    cudaGetSymbolAddress((void**)&vhb,  g_vh);
    cudaGetSymbolAddress((void**)&vlb,  g_vl);

    cudaFuncSetAttribute(gemm_tc, cudaFuncAttributeMaxDynamicSharedMemorySize, TC_SMEM_BYTES);
    cudaFuncSetAttribute(attn_mma_kernel, cudaFuncAttributeMaxDynamicSharedMemorySize, ATT_SMEM);

    // packed weight offsets: per stream [q(2048);k(1024);v(1024)] then o, gate, up, down
    const size_t QN   = (size_t)NHC * DC;     // 4194304
    const size_t KN   = (size_t)KHC * DC;     // 2097152
    const size_t FN   = (size_t)FC * DC;      // 16777216
    const size_t QKVN = QN + 2 * KN;          // 8388608
    const size_t oqkv0 = 0, oqkv1 = QKVN;
    const size_t oo0 = 2 * QKVN,      oo1 = oo0 + QN;
    const size_t og0 = oo1 + QN,      og1 = og0 + FN;
    const size_t ou0 = og1 + FN,      ou1 = ou0 + FN;
    const size_t od0 = ou1 + FN,      od1 = od0 + FN;

    // 0. weight fp32 -> bf16 hi/lo (q,k,v packed per stream)
    cvt_split_kernel<<<(int)(QN / 2048), 256>>>(q0w, wh + oqkv0, wl + oqkv0, (int)QN);
    cvt_split_kernel<<<(int)(KN / 2048), 256>>>(k0w, wh + oqkv0 + QN, wl + oqkv0 + QN, (int)KN);
    cvt_split_kernel<<<(int)(KN / 2048), 256>>>(v0w, wh + oqkv0 + QN + KN, wl + oqkv0 + QN + KN, (int)KN);
    cvt_split_kernel<<<(int)(QN / 2048), 256>>>(q1w, wh + oqkv1, wl + oqkv1, (int)QN);
    cvt_split_kernel<<<(int)(KN / 2048), 256>>>(k1w, wh + oqkv1 + QN, wl + oqkv1 + QN, (int)KN);
    cvt_split_kernel<<<(int)(KN / 2048), 256>>>(v1w, wh + oqkv1 + QN + KN, wl + oqkv1 + QN + KN, (int)KN);
    cvt_split_kernel<<<(int)(QN / 2048), 256>>>(o0w, wh + oo0, wl + oo0, (int)QN);
    cvt_split_kernel<<<(int)(QN / 2048), 256>>>(o1w, wh + oo1, wl + oo1, (int)QN);
    cvt_split_kernel<<<(int)(FN / 2048), 256>>>(gt0, wh + og0, wl + og0, (int)FN);
    cvt_split_kernel<<<(int)(FN / 2048), 256>>>(gt1, wh + og1, wl + og1, (int)FN);
    cvt_split_kernel<<<(int)(FN / 2048), 256>>>(up0, wh + ou0, wl + ou0, (int)FN);
    cvt_split_kernel<<<(int)(FN / 2048), 256>>>(up1, wh + ou1, wl + ou1, (int)FN);
    cvt_split_kernel<<<(int)(FN / 2048), 256>>>(dw0, wh + od0, wl + od0, (int)FN);
    cvt_split_kernel<<<(int)(FN / 2048), 256>>>(dw1, wh + od1, wl + od1, (int)FN);

    // 1. pre-attn rmsnorm -> bf16 hi/lo
    rmsnorm_kernel<<<BB * T0C, 256>>>(x0, preh, prel, pa0, 0, 0);
    rmsnorm_kernel<<<BB * T0C, 256>>>(x1, preh, prel, pa1, 1, 0);

    // 2. fused QKV projection (packed Nout=4096)
    {
        dim3 g(4096 / GBN, T0C / GBM, 4);
        gemm_tc<<<g, 256, TC_SMEM_BYTES>>>(preh, prel, wh + oqkv0, wl + oqkv0, wh + oqkv1, wl + oqkv1,
                                           qkv, DC, 4096, 0, 0, 0, 0, 0, 0, 0, 0);
    }

    // 3. RoPE + scale + split to bf16 hi/lo
    rope_split_kernel<<<BB * TOTC, 256>>>(qkv, pos, qhb, qlb, khb, klb, vhb, vlb);

    // 4. attention (mma.sync flash) -> writes ench/encl directly
    {
        dim3 ga(TOTC / ATT_BM, NC, BB);
        attn_mma_kernel<<<ga, 256, ATT_SMEM>>>(qhb, qlb, khb, klb, vhb, vlb, ench, encl);
    }

    // 5. O projection + residual
    {
        dim3 go(DC / GBN, T0C / GBM, 4);
        gemm_tc<<<go, 256, TC_SMEM_BYTES>>>(ench, encl, wh + oo0, wl + oo0, wh + oo1, wl + oo1,
                                            res, NHC, DC, 2, x0, x1, 0, 0, 0, 0, 0);
    }

    // 6. pre-ffw rmsnorm -> bf16 hi/lo
    rmsnorm_kernel<<<BB * T0C, 256>>>(res, hidh, hidl, pf0, 0, 1);
    rmsnorm_kernel<<<BB * T0C, 256>>>(res, hidh, hidl, pf1, 1, 1);

    // 7. gate (gelu) then up (fused gelu(gate)*up split) projections
    {
        dim3 gf(FC / GBN, T0C / GBM, 4);
        gemm_tc<<<gf, 256, TC_SMEM_BYTES>>>(hidh, hidl, wh + og0, wl + og0, wh + og1, wl + og1,
                                            gate, DC, FC, 1, 0, 0, 0, 0, 0, 0, 0);
        gemm_tc<<<gf, 256, TC_SMEM_BYTES>>>(hidh, hidl, wh + ou0, wl + ou0, wh + ou1, wl + ou1,
                                            gate, DC, FC, 3, 0, 0, 0, 0, gate, guh, gul);
    }

    // 8. down projection + residual -> out (stream-major)
    {
        dim3 gd(DC / GBN, T0C / GBM, 4);
        gemm_tc<<<gd, 256, TC_SMEM_BYTES>>>(guh, gul, wh + od0, wl + od0, wh + od1, wl + od1,
                                            out, FC, DC, 2, res, 0, 1, 1, 0, 0, 0);
    }
}

// round 6
// speedup vs baseline: 3.7081x; 1.0200x over previous
#include <cuda_runtime.h>
#include <cuda_bf16.h>
#include <math.h>
#include <float.h>
#include <stdint.h>

// ---------------- problem constants ----------------
#define BB   2
#define T0C  1024
#define TOTC 2048
#define DC   2048
#define NC   16
#define KC   8
#define HC   128
#define FC   8192
#define NHC  2048   // N*H
#define KHC  1024   // K*H
#define GC   2      // N/K

typedef __nv_bfloat16 bf16;

// ---------------- helpers ----------------
__device__ __forceinline__ uint32_t smem_to_u32(const void* p) {
    uint32_t a;
    asm("{ .reg .u64 t; cvta.to.shared.u64 t, %1; cvt.u32.u64 %0, t; }" : "=r"(a) : "l"(p));
    return a;
}
#define LDSM4(r, addr) \
    asm volatile("ldmatrix.sync.aligned.m8n8.x4.shared.b16 {%0,%1,%2,%3}, [%4];" \
        : "=r"((r)[0]), "=r"((r)[1]), "=r"((r)[2]), "=r"((r)[3]) : "r"(addr))
#define LDSM4T(r, addr) \
    asm volatile("ldmatrix.sync.aligned.m8n8.x4.trans.shared.b16 {%0,%1,%2,%3}, [%4];" \
        : "=r"((r)[0]), "=r"((r)[1]), "=r"((r)[2]), "=r"((r)[3]) : "r"(addr))
#define MMA16816(d, a, b0, b1) \
    asm volatile("mma.sync.aligned.m16n8k16.row.col.f32.bf16.bf16.f32 " \
        "{%0,%1,%2,%3},{%4,%5,%6,%7},{%8,%9},{%0,%1,%2,%3};" \
        : "+f"((d)[0]), "+f"((d)[1]), "+f"((d)[2]), "+f"((d)[3]) \
        : "r"((a)[0]), "r"((a)[1]), "r"((a)[2]), "r"((a)[3]), "r"(b0), "r"(b1))
#define CP_ASYNC16(saddr, gaddr) \
    asm volatile("cp.async.cg.shared.global [%0], [%1], 16;" :: "r"(saddr), "l"(gaddr))
#define CP_COMMIT() asm volatile("cp.async.commit_group;" ::: "memory")
#define CP_WAIT(n)  asm volatile("cp.async.wait_group %0;" :: "n"(n) : "memory")

// ---------------- scratch (device globals; no runtime alloc) ----------------
__device__ float g_qkv [(size_t)BB*TOTC*4096];   // packed q(2048)|k(1024)|v(1024)
__device__ float g_res [(size_t)BB*TOTC*DC];
__device__ float g_gate[(size_t)BB*TOTC*FC];

__device__ bf16 g_preh[(size_t)BB*TOTC*DC];
__device__ bf16 g_prel[(size_t)BB*TOTC*DC];
__device__ bf16 g_hidh[(size_t)BB*TOTC*DC];
__device__ bf16 g_hidl[(size_t)BB*TOTC*DC];
__device__ bf16 g_ench[(size_t)BB*TOTC*NHC];
__device__ bf16 g_encl[(size_t)BB*TOTC*NHC];
__device__ bf16 g_guh [(size_t)BB*TOTC*FC];
__device__ bf16 g_gul [(size_t)BB*TOTC*FC];
__device__ bf16 g_qh  [(size_t)BB*TOTC*NHC];
__device__ bf16 g_ql  [(size_t)BB*TOTC*NHC];
__device__ bf16 g_kh  [(size_t)BB*TOTC*KHC];
__device__ bf16 g_kl  [(size_t)BB*TOTC*KHC];
__device__ bf16 g_vh  [(size_t)BB*TOTC*KHC];
__device__ bf16 g_vl  [(size_t)BB*TOTC*KHC];
__device__ bf16 g_wh  [125829120];
__device__ bf16 g_wl  [125829120];

// ---------------- elementwise helpers ----------------
__device__ __forceinline__ float gelu_tanh(float x) {
    float x3 = x * x * x;
    return 0.5f * x * (1.0f + tanhf(0.7978845608028654f * (x + 0.044715f * x3)));
}
__device__ __forceinline__ void split_store(float v, bf16* h, bf16* l) {
    bf16 hh = __float2bfloat16(v);
    *h = hh;
    *l = __float2bfloat16(v - __bfloat162float(hh));
}
__device__ __forceinline__ uint32_t pack_split2(float a, float b, uint32_t& lo) {
    bf16 ha = __float2bfloat16(a), hb = __float2bfloat16(b);
    bf16 la = __float2bfloat16(a - __bfloat162float(ha));
    bf16 lb = __float2bfloat16(b - __bfloat162float(hb));
    lo = (uint32_t)__bfloat16_as_ushort(la) | ((uint32_t)__bfloat16_as_ushort(lb) << 16);
    return (uint32_t)__bfloat16_as_ushort(ha) | ((uint32_t)__bfloat16_as_ushort(hb) << 16);
}

// ---------------- fused weight conversion (single launch) ----------------
#define NJOBS 14
struct CvtJobs {
    const float* src[NJOBS];
    bf16* h[NJOBS];
    bf16* l[NJOBS];
    int startblk[NJOBS + 1];
};

__global__ void cvt_all_kernel(CvtJobs J)
{
    int bid = blockIdx.x;
    int j = 0;
    #pragma unroll
    for (int t = 1; t < NJOBS; ++t) if (bid >= J.startblk[t]) j = t;
    int i = ((bid - J.startblk[j]) * 256 + threadIdx.x) * 8;
    const float* src = J.src[j];
    float4 a = *(const float4*)(src + i);
    float4 b = *(const float4*)(src + i + 4);
    uint4 hv, lv;
    hv.x = pack_split2(a.x, a.y, lv.x);
    hv.y = pack_split2(a.z, a.w, lv.y);
    hv.z = pack_split2(b.x, b.y, lv.z);
    hv.w = pack_split2(b.z, b.w, lv.w);
    *(uint4*)(J.h[j] + i) = hv;
    *(uint4*)(J.l[j] + i) = lv;
}

__global__ void pad_kernel() {}

// ---------------- rmsnorm pair (both streams in one launch) ----------------
__global__ void rmsnorm2_kernel(const float* __restrict__ s0, const float* __restrict__ s1,
                                bf16* __restrict__ dsth, bf16* __restrict__ dstl,
                                const float* __restrict__ sc0, const float* __restrict__ sc1,
                                int srcmode)
{
    int istream = blockIdx.y;
    int row = blockIdx.x;               // 0 .. B*T0-1
    int b = row / T0C, t = row % T0C;
    size_t crow = (size_t)b * TOTC + (size_t)istream * T0C + t;
    const float* base = istream ? s1 : s0;
    const float* scale = istream ? sc1 : sc0;
    const float* s = base + (srcmode ? crow : (size_t)row) * DC;
    bf16* oh = dsth + crow * DC;
    bf16* ol = dstl + crow * DC;

    __shared__ float red[256];
    float ss = 0.f;
    for (int d = threadIdx.x; d < DC; d += 256) { float v = s[d]; ss += v * v; }
    red[threadIdx.x] = ss;
    __syncthreads();
    for (int st = 128; st > 0; st >>= 1) {
        if (threadIdx.x < st) red[threadIdx.x] += red[threadIdx.x + st];
        __syncthreads();
    }
    float inv = rsqrtf(red[0] * (1.0f / DC) + 1e-6f);
    for (int d = threadIdx.x; d < DC; d += 256) {
        float v = s[d] * inv * (1.0f + scale[d]);
        split_store(v, oh + d, ol + d);
    }
}

// ---------------- rope + split (reads packed qkv; q,k roped+split; v split) ----------------
__global__ void rope_split_kernel(const float* __restrict__ qkv, const int* __restrict__ positions,
                                  bf16* __restrict__ qh, bf16* __restrict__ ql,
                                  bf16* __restrict__ kh, bf16* __restrict__ kl,
                                  bf16* __restrict__ vh, bf16* __restrict__ vl)
{
    int row = blockIdx.x;                       // b*TOT + t
    float pos = (float)positions[row];
    const float QSCALE = 0.08838834764831845f;  // 128^-0.5
    const float* src = qkv + (size_t)row * 4096;
    for (int w = threadIdx.x; w < (NC + KC) * 64; w += 256) {
        int head = w >> 6;
        int j = w & 63;
        float ts = powf(10000.0f, (float)j * (1.0f / 64.0f));
        float sn, cs;
        sincosf(pos / ts, &sn, &cs);
        if (head < NC) {
            float x1 = src[head * HC + j], x2 = src[head * HC + j + 64];
            size_t o = ((size_t)row * NC + head) * HC;
            split_store((x1 * cs - x2 * sn) * QSCALE, qh + o + j, ql + o + j);
            split_store((x2 * cs + x1 * sn) * QSCALE, qh + o + j + 64, ql + o + j + 64);
        } else {
            int kkh = head - NC;
            float x1 = src[2048 + kkh * HC + j], x2 = src[2048 + kkh * HC + j + 64];
            size_t o = ((size_t)row * KC + kkh) * HC;
            split_store(x1 * cs - x2 * sn, kh + o + j, kl + o + j);
            split_store(x2 * cs + x1 * sn, kh + o + j + 64, kl + o + j + 64);
        }
    }
    for (int idx = threadIdx.x; idx < KHC; idx += 256) {
        size_t o = (size_t)row * KHC + idx;
        split_store(src[3072 + idx], vh + o, vl + o);
    }
}

// ---------------- mma.sync GEMM: C = A @ W^T (+epilogue), bf16x3 split ----------------
// CTA 128x256, warp tile 64x64, GBK=32, 3-stage cp.async pipeline, 1 barrier/chunk.
// epi: 0 none, 1 gelu, 2 +residual, 3 gelu-gate-mul-split (reads G fp32, writes GH/GL bf16)
#define GBM 128
#define GBN 256
#define GBK 32
#define GSTAGES 3
#define ROWB   80
#define TILEA_B (128 * ROWB)                 // 10240
#define TILEW_B (256 * ROWB)                 // 20480
#define STAGE_B (2 * TILEA_B + 2 * TILEW_B)  // 61440
#define TC_SMEM_BYTES (GSTAGES * STAGE_B)    // 184320

__global__ __launch_bounds__(256, 1)
void gemm_tc(const bf16* __restrict__ Ah_, const bf16* __restrict__ Al_,
             const bf16* __restrict__ W0h, const bf16* __restrict__ W0l,
             const bf16* __restrict__ W1h, const bf16* __restrict__ W1l,
             float* __restrict__ C_, int Kd, int Nout, int epi,
             const float* __restrict__ R0, const float* __restrict__ R1,
             int resmode, int outmode,
             const float* __restrict__ G_, bf16* __restrict__ GH_, bf16* __restrict__ GL_)
{
    extern __shared__ char smem[];
    const uint32_t s0 = smem_to_u32(smem);

    const int tid = threadIdx.x;
    const int lane = tid & 31, warp = tid >> 5;
    const int wm = warp >> 2, wn = warp & 3;      // warp tile: 64 (m) x 64 (n)

    const int z = blockIdx.z, i = z >> 1, b = z & 1;
    const size_t arow0 = (size_t)b * TOTC + (size_t)i * T0C;
    const bf16* Ah = Ah_ + arow0 * Kd;
    const bf16* Al = Al_ + arow0 * Kd;
    const bf16* Wh = i ? W1h : W0h;
    const bf16* Wl = i ? W1l : W0l;
    float* C = (outmode == 0) ? (C_ + arow0 * (size_t)Nout)
                              : (C_ + ((size_t)i * BB * T0C + (size_t)b * T0C) * (size_t)Nout);
    const float* R = 0;
    if (epi == 2) R = (resmode == 0) ? ((i ? R1 : R0) + (size_t)b * T0C * Nout)
                                     : (R0 + arow0 * (size_t)Nout);
    const float* G = 0; bf16* GH = 0; bf16* GL = 0;
    if (epi == 3) { G = G_ + arow0 * (size_t)Nout; GH = GH_ + arow0 * (size_t)Nout; GL = GL_ + arow0 * (size_t)Nout; }

    const int m0 = blockIdx.y * GBM, n0 = blockIdx.x * GBN;
    const int nk = Kd / GBK;

    #define ISSUE_STAGE(cc) do {                                                 \
        int kk0 = (cc) * GBK;                                                    \
        uint32_t sbase = s0 + ((cc) % GSTAGES) * STAGE_B;                        \
        _Pragma("unroll")                                                        \
        for (int it = 0; it < 12; ++it) {                                        \
            int idx = tid + it * 256;                                            \
            const bf16* gp; uint32_t sa;                                         \
            if (idx < 1024) {                                                    \
                int tt = idx >> 9;                                               \
                int cid = idx & 511;                                             \
                int row = cid >> 2, ch = cid & 3;                                \
                sa = sbase + tt * TILEA_B + row * ROWB + ch * 16;                \
                gp = (tt ? Al : Ah) + (size_t)(m0 + row) * Kd + kk0 + ch * 8;    \
            } else {                                                             \
                int cid = idx - 1024;                                            \
                int tt = cid >> 10;                                              \
                cid &= 1023;                                                     \
                int row = cid >> 2, ch = cid & 3;                                \
                sa = sbase + 2 * TILEA_B + tt * TILEW_B + row * ROWB + ch * 16;  \
                gp = (tt ? Wl : Wh) + (size_t)(n0 + row) * Kd + kk0 + ch * 8;    \
            }                                                                    \
            CP_ASYNC16(sa, gp);                                                  \
        }                                                                        \
        CP_COMMIT();                                                             \
    } while (0)

    float acc[4][8][4];
    #pragma unroll
    for (int mf = 0; mf < 4; ++mf)
        #pragma unroll
        for (int nf = 0; nf < 8; ++nf)
            #pragma unroll
            for (int r = 0; r < 4; ++r) acc[mf][nf][r] = 0.f;

    const int a_row = wm * 64 + (lane & 15);
    const int a_cj  = lane >> 4;
    const int b_row = wn * 64 + (lane & 7) + ((lane >> 4) & 1) * 8;
    const int b_cj  = (lane >> 3) & 1;

    ISSUE_STAGE(0);
    ISSUE_STAGE(1);

    for (int c = 0; c < nk; ++c) {
        if (c + 1 < nk) CP_WAIT(1); else CP_WAIT(0);
        __syncthreads();
        if (c + 2 < nk) ISSUE_STAGE(c + 2);

        uint32_t sbase = s0 + (c % GSTAGES) * STAGE_B;
        uint32_t aH = sbase, aL = sbase + TILEA_B;
        uint32_t bH = sbase + 2 * TILEA_B, bL = bH + TILEW_B;

        #pragma unroll
        for (int ks = 0; ks < 2; ++ks) {
            uint32_t ah[4][4], al[4][4];
            uint32_t aoff = (uint32_t)(a_row * ROWB + (ks * 2 + a_cj) * 16);
            #pragma unroll
            for (int mf = 0; mf < 4; ++mf) {
                LDSM4(ah[mf], aH + aoff + mf * (16 * ROWB));
                LDSM4(al[mf], aL + aoff + mf * (16 * ROWB));
            }
            uint32_t boff = (uint32_t)(b_row * ROWB + (ks * 2 + b_cj) * 16);
            #pragma unroll
            for (int nf2 = 0; nf2 < 4; ++nf2) {
                uint32_t bh[4], bl[4];
                LDSM4(bh, bH + boff + nf2 * (16 * ROWB));
                LDSM4(bl, bL + boff + nf2 * (16 * ROWB));
                #pragma unroll
                for (int mf = 0; mf < 4; ++mf) {
                    MMA16816(acc[mf][nf2 * 2], ah[mf], bh[0], bh[1]);
                    MMA16816(acc[mf][nf2 * 2], al[mf], bh[0], bh[1]);
                    MMA16816(acc[mf][nf2 * 2], ah[mf], bl[0], bl[1]);
                    MMA16816(acc[mf][nf2 * 2 + 1], ah[mf], bh[2], bh[3]);
                    MMA16816(acc[mf][nf2 * 2 + 1], al[mf], bh[2], bh[3]);
                    MMA16816(acc[mf][nf2 * 2 + 1], ah[mf], bl[2], bl[3]);
                }
            }
        }
    }

    // epilogue
    #pragma unroll
    for (int mf = 0; mf < 4; ++mf) {
        int r0 = m0 + wm * 64 + mf * 16 + (lane >> 2);
        #pragma unroll
        for (int nf = 0; nf < 8; ++nf) {
            int col = n0 + wn * 64 + nf * 8 + (lane & 3) * 2;
            float2 v0 = make_float2(acc[mf][nf][0], acc[mf][nf][1]);
            float2 v1 = make_float2(acc[mf][nf][2], acc[mf][nf][3]);
            if (epi == 3) {
                float2 g0 = *(const float2*)(G + (size_t)r0 * Nout + col);
                float2 g1 = *(const float2*)(G + (size_t)(r0 + 8) * Nout + col);
                uint32_t lo0, lo1;
                uint32_t hi0 = pack_split2(v0.x * g0.x, v0.y * g0.y, lo0);
                uint32_t hi1 = pack_split2(v1.x * g1.x, v1.y * g1.y, lo1);
                *(uint32_t*)((char*)GH + ((size_t)r0 * Nout + col) * 2)       = hi0;
                *(uint32_t*)((char*)GL + ((size_t)r0 * Nout + col) * 2)       = lo0;
                *(uint32_t*)((char*)GH + ((size_t)(r0 + 8) * Nout + col) * 2) = hi1;
                *(uint32_t*)((char*)GL + ((size_t)(r0 + 8) * Nout + col) * 2) = lo1;
            } else {
                if (epi == 1) {
                    v0.x = gelu_tanh(v0.x); v0.y = gelu_tanh(v0.y);
                    v1.x = gelu_tanh(v1.x); v1.y = gelu_tanh(v1.y);
                } else if (epi == 2) {
                    float2 r4a = *(const float2*)(R + (size_t)r0 * Nout + col);
                    float2 r4b = *(const float2*)(R + (size_t)(r0 + 8) * Nout + col);
                    v0.x += r4a.x; v0.y += r4a.y;
                    v1.x += r4b.x; v1.y += r4b.y;
                }
                *(float2*)(C + (size_t)r0 * Nout + col)       = v0;
                *(float2*)(C + (size_t)(r0 + 8) * Nout + col) = v1;
            }
        }
    }
}

// ---------------- attention: mma.sync flash kernel, bf16 hi/lo splits ----------------
#define ATT_BM 128
#define ATT_BN 32
#define QROWB 272
#define KROWB 272
#define PROWB 80
#define SQH 0
#define SQL 34816
#define SKV 69632
#define KVTILE 8704
#define SPH 139264
#define SPL 149504
#define ATT_SMEM 159744
#define NEGA (-1e30f)

__global__ __launch_bounds__(256, 1)
void attn_mma_kernel(const bf16* __restrict__ qh, const bf16* __restrict__ ql,
                     const bf16* __restrict__ kh, const bf16* __restrict__ kl,
                     const bf16* __restrict__ vh, const bf16* __restrict__ vl,
                     bf16* __restrict__ ench, bf16* __restrict__ encl)
{
    extern __shared__ char smem[];
    const uint32_t s0u = smem_to_u32(smem);
    const int tid = threadIdx.x, lane = tid & 31, w = tid >> 5;
    const int bq = blockIdx.z;
    const int n = blockIdx.y;
    const int kk = n >> 1;
    const int t0 = ((int)gridDim.x - 1 - (int)blockIdx.x) * ATT_BM;   // big CTAs first
    const size_t bT = (size_t)bq * TOTC;

    // Q tile hi/lo -> smem
    #pragma unroll
    for (int it = 0; it < 16; ++it) {
        int idx = tid + it * 256;
        int tens = idx >> 11, row = (idx >> 4) & 127, ch = idx & 15;
        const bf16* src = (tens ? ql : qh) + ((bT + t0 + row) * NC + n) * HC + ch * 8;
        CP_ASYNC16(s0u + (tens ? SQL : SQH) + row * QROWB + ch * 16, src);
    }
    CP_COMMIT();

    #define LOAD_KV(j) do {                                                        \
        int _bf = (j) & 1; int _s0 = (j) * ATT_BN;                                 \
        _Pragma("unroll")                                                          \
        for (int it = 0; it < 8; ++it) {                                           \
            int idx = tid + it * 256;                                              \
            int tt = idx >> 9, cid = idx & 511, row = cid >> 4, ch = cid & 15;     \
            const bf16* srcp;                                                      \
            if (tt == 0) srcp = kh; else if (tt == 1) srcp = kl;                   \
            else if (tt == 2) srcp = vh; else srcp = vl;                           \
            srcp += ((bT + _s0 + row) * KC + kk) * HC + ch * 8;                    \
            CP_ASYNC16(s0u + SKV + (_bf * 4 + tt) * KVTILE + row * KROWB + ch * 16, srcp); \
        }                                                                          \
        CP_COMMIT();                                                               \
    } while (0)

    const int nb = t0 / ATT_BN + 4;
    LOAD_KV(0);

    const int tw = t0 + w * 16;
    const int r0 = lane >> 2;                 // warp-local rows r0, r0+8
    float oacc[16][4];
    #pragma unroll
    for (int a = 0; a < 16; ++a) { oacc[a][0] = oacc[a][1] = oacc[a][2] = oacc[a][3] = 0.f; }
    float mrow0 = NEGA, mrow1 = NEGA, lrow0 = 0.f, lrow1 = 0.f;

    const uint32_t psh_base = s0u + SPH + (w * 16) * PROWB;
    const uint32_t psl_base = s0u + SPL + (w * 16) * PROWB;

    for (int j = 0; j < nb; ++j) {
        CP_WAIT(0);
        __syncthreads();
        if (j + 1 < nb) LOAD_KV(j + 1);

        const int sblk = j * ATT_BN;
        const int bf = j & 1;
        const uint32_t kH = s0u + SKV + (bf * 4 + 0) * KVTILE;
        const uint32_t kL = s0u + SKV + (bf * 4 + 1) * KVTILE;
        const uint32_t vH = s0u + SKV + (bf * 4 + 2) * KVTILE;
        const uint32_t vL = s0u + SKV + (bf * 4 + 3) * KVTILE;

        if (sblk <= tw + 15) {                 // warp has unmasked rows
            // ---- S = Q K^T (bf16x3) ----
            float sacc[4][4];
            #pragma unroll
            for (int nf = 0; nf < 4; ++nf) { sacc[nf][0]=sacc[nf][1]=sacc[nf][2]=sacc[nf][3]=0.f; }
            const uint32_t aoff_base = (uint32_t)((w * 16 + (lane & 15)) * QROWB + (lane >> 4) * 16);
            const uint32_t brow = (uint32_t)((lane & 7) + ((lane >> 4) & 1) * 8);
            const uint32_t bco  = (uint32_t)(((lane >> 3) & 1) * 16);
            #pragma unroll
            for (int ks = 0; ks < 8; ++ks) {
                uint32_t ah[4], al[4], bh0[4], bh1[4], bl0[4], bl1[4];
                uint32_t aoff = aoff_base + ks * 32;
                LDSM4(ah, s0u + SQH + aoff);
                LDSM4(al, s0u + SQL + aoff);
                uint32_t boff0 = brow * KROWB + ks * 32 + bco;
                uint32_t boff1 = boff0 + 16 * KROWB;
                LDSM4(bh0, kH + boff0); LDSM4(bh1, kH + boff1);
                LDSM4(bl0, kL + boff0); LDSM4(bl1, kL + boff1);
                MMA16816(sacc[0], ah, bh0[0], bh0[1]);
                MMA16816(sacc[0], al, bh0[0], bh0[1]);
                MMA16816(sacc[0], ah, bl0[0], bl0[1]);
                MMA16816(sacc[1], ah, bh0[2], bh0[3]);
                MMA16816(sacc[1], al, bh0[2], bh0[3]);
                MMA16816(sacc[1], ah, bl0[2], bl0[3]);
                MMA16816(sacc[2], ah, bh1[0], bh1[1]);
                MMA16816(sacc[2], al, bh1[0], bh1[1]);
                MMA16816(sacc[2], ah, bl1[0], bl1[1]);
                MMA16816(sacc[3], ah, bh1[2], bh1[3]);
                MMA16816(sacc[3], al, bh1[2], bh1[3]);
                MMA16816(sacc[3], ah, bl1[2], bl1[3]);
            }

            // ---- causal mask (diagonal blocks only) ----
            if (sblk + ATT_BN - 1 > tw) {
                #pragma unroll
                for (int nf = 0; nf < 4; ++nf) {
                    int sg = sblk + nf * 8 + (lane & 3) * 2;
                    int tg0 = tw + r0, tg1 = tg0 + 8;
                    if (sg     > tg0) sacc[nf][0] = NEGA;
                    if (sg + 1 > tg0) sacc[nf][1] = NEGA;
                    if (sg     > tg1) sacc[nf][2] = NEGA;
                    if (sg + 1 > tg1) sacc[nf][3] = NEGA;
                }
            }

            // ---- online softmax ----
            float mx0 = NEGA, mx1 = NEGA;
            #pragma unroll
            for (int nf = 0; nf < 4; ++nf) {
                mx0 = fmaxf(mx0, fmaxf(sacc[nf][0], sacc[nf][1]));
                mx1 = fmaxf(mx1, fmaxf(sacc[nf][2], sacc[nf][3]));
            }
            mx0 = fmaxf(mx0, __shfl_xor_sync(0xffffffffu, mx0, 1));
            mx0 = fmaxf(mx0, __shfl_xor_sync(0xffffffffu, mx0, 2));
            mx1 = fmaxf(mx1, __shfl_xor_sync(0xffffffffu, mx1, 1));
            mx1 = fmaxf(mx1, __shfl_xor_sync(0xffffffffu, mx1, 2));
            float mn0 = fmaxf(mrow0, mx0), mn1 = fmaxf(mrow1, mx1);
            float al0 = __expf(mrow0 - mn0), al1 = __expf(mrow1 - mn1);
            float se0 = 0.f, se1 = 0.f;
            #pragma unroll
            for (int nf = 0; nf < 4; ++nf) {
                float p0 = __expf(sacc[nf][0] - mn0);
                float p1 = __expf(sacc[nf][1] - mn0);
                float p2 = __expf(sacc[nf][2] - mn1);
                float p3 = __expf(sacc[nf][3] - mn1);
                se0 += p0 + p1; se1 += p2 + p3;
                uint32_t pcol = (uint32_t)((nf * 8 + (lane & 3) * 2) * 2);
                uint32_t lo0, lo1;
                uint32_t hi0 = pack_split2(p0, p1, lo0);
                uint32_t hi1 = pack_split2(p2, p3, lo1);
                *(uint32_t*)(smem + (psh_base - s0u) + r0 * PROWB + pcol)       = hi0;
                *(uint32_t*)(smem + (psl_base - s0u) + r0 * PROWB + pcol)       = lo0;
                *(uint32_t*)(smem + (psh_base - s0u) + (r0 + 8) * PROWB + pcol) = hi1;
                *(uint32_t*)(smem + (psl_base - s0u) + (r0 + 8) * PROWB + pcol) = lo1;
            }
            se0 += __shfl_xor_sync(0xffffffffu, se0, 1);
            se0 += __shfl_xor_sync(0xffffffffu, se0, 2);
            se1 += __shfl_xor_sync(0xffffffffu, se1, 1);
            se1 += __shfl_xor_sync(0xffffffffu, se1, 2);
            mrow0 = mn0; mrow1 = mn1;
            lrow0 = lrow0 * al0 + se0;
            lrow1 = lrow1 * al1 + se1;
            #pragma unroll
            for (int a = 0; a < 16; ++a) {
                oacc[a][0] *= al0; oacc[a][1] *= al0;
                oacc[a][2] *= al1; oacc[a][3] *= al1;
            }
            __syncwarp();

            // ---- O += P V (bf16x3) ----
            const uint32_t vrow = (uint32_t)((lane & 7) + ((lane >> 3) & 1) * 8);
            const uint32_t vco  = (uint32_t)((lane >> 4) * 16);
            #pragma unroll
            for (int ks2 = 0; ks2 < 2; ++ks2) {
                uint32_t ph[4], pl[4];
                uint32_t pa = (uint32_t)((lane & 15) * PROWB + (ks2 * 16 + (lane >> 4) * 8) * 2);
                LDSM4(ph, psh_base + pa);
                LDSM4(pl, psl_base + pa);
                #pragma unroll
                for (int hf = 0; hf < 8; ++hf) {
                    uint32_t bvh[4], bvl[4];
                    uint32_t voff = (ks2 * 16 + vrow) * KROWB + hf * 32 + vco;
                    LDSM4T(bvh, vH + voff);
                    LDSM4T(bvl, vL + voff);
                    MMA16816(oacc[2*hf],     ph, bvh[0], bvh[1]);
                    MMA16816(oacc[2*hf],     pl, bvh[0], bvh[1]);
                    MMA16816(oacc[2*hf],     ph, bvl[0], bvl[1]);
                    MMA16816(oacc[2*hf + 1], ph, bvh[2], bvh[3]);
                    MMA16816(oacc[2*hf + 1], pl, bvh[2], bvh[3]);
                    MMA16816(oacc[2*hf + 1], ph, bvl[2], bvl[3]);
                }
            }
        }
    }

    // ---- epilogue: normalize + split-store enc ----
    float inv0 = 1.0f / lrow0, inv1 = 1.0f / lrow1;
    #pragma unroll
    for (int nt = 0; nt < 16; ++nt) {
        int hcol = nt * 8 + (lane & 3) * 2;
        size_t o0 = ((bT + tw + r0) * NC + n) * HC + hcol;
        size_t o1 = ((bT + tw + r0 + 8) * NC + n) * HC + hcol;
        uint32_t lo0, lo1;
        uint32_t hi0 = pack_split2(oacc[nt][0] * inv0, oacc[nt][1] * inv0, lo0);
        uint32_t hi1 = pack_split2(oacc[nt][2] * inv1, oacc[nt][3] * inv1, lo1);
        *(uint32_t*)((char*)ench + o0 * 2) = hi0;
        *(uint32_t*)((char*)encl + o0 * 2) = lo0;
        *(uint32_t*)((char*)ench + o1 * 2) = hi1;
        *(uint32_t*)((char*)encl + o1 * 2) = lo1;
    }
}

// ---------------- host ----------------
extern "C" void kernel_launch(void* const* d_in, const int* in_sizes, int n_in,
                              void* d_out, int out_size)
{
    (void)in_sizes; (void)n_in; (void)out_size;
    const float* x0  = (const float*)d_in[0];
    const float* x1  = (const float*)d_in[1];
    const int*   pos = (const int*)  d_in[2];
    const float* q0w = (const float*)d_in[4];
    const float* q1w = (const float*)d_in[5];
    const float* k0w = (const float*)d_in[6];
    const float* k1w = (const float*)d_in[7];
    const float* v0w = (const float*)d_in[8];
    const float* v1w = (const float*)d_in[9];
    const float* o0w = (const float*)d_in[10];
    const float* o1w = (const float*)d_in[11];
    const float* gt0 = (const float*)d_in[12];
    const float* gt1 = (const float*)d_in[13];
    const float* up0 = (const float*)d_in[14];
    const float* up1 = (const float*)d_in[15];
    const float* dw0 = (const float*)d_in[16];
    const float* dw1 = (const float*)d_in[17];
    const float* pa0 = (const float*)d_in[18];
    const float* pa1 = (const float*)d_in[19];
    const float* pf0 = (const float*)d_in[20];
    const float* pf1 = (const float*)d_in[21];
    float* out = (float*)d_out;

    float *qkv, *res, *gate;
    bf16 *preh, *prel, *hidh, *hidl, *ench, *encl, *guh, *gul, *wh, *wl;
    bf16 *qhb, *qlb, *khb, *klb, *vhb, *vlb;
    cudaGetSymbolAddress((void**)&qkv,  g_qkv);
    cudaGetSymbolAddress((void**)&res,  g_res);
    cudaGetSymbolAddress((void**)&gate, g_gate);
    cudaGetSymbolAddress((void**)&preh, g_preh);
    cudaGetSymbolAddress((void**)&prel, g_prel);
    cudaGetSymbolAddress((void**)&hidh, g_hidh);
    cudaGetSymbolAddress((void**)&hidl, g_hidl);
    cudaGetSymbolAddress((void**)&ench, g_ench);
    cudaGetSymbolAddress((void**)&encl, g_encl);
    cudaGetSymbolAddress((void**)&guh,  g_guh);
    cudaGetSymbolAddress((void**)&gul,  g_gul);
    cudaGetSymbolAddress((void**)&wh,   g_wh);
    cudaGetSymbolAddress((void**)&wl,   g_wl);
    cudaGetSymbolAddress((void**)&qhb,  g_qh);
    cudaGetSymbolAddress((void**)&qlb,  g_ql);
    cudaGetSymbolAddress((void**)&khb,  g_kh);
    cudaGetSymbolAddress((void**)&klb,  g_kl);
    cudaGetSymbolAddress((void**)&vhb,  g_vh);
    cudaGetSymbolAddress((void**)&vlb,  g_vl);

    cudaFuncSetAttribute(gemm_tc, cudaFuncAttributeMaxDynamicSharedMemorySize, TC_SMEM_BYTES);
    cudaFuncSetAttribute(attn_mma_kernel, cudaFuncAttributeMaxDynamicSharedMemorySize, ATT_SMEM);

    // packed weight offsets: per stream [q(2048);k(1024);v(1024)] then o, gate, up, down
    const size_t QN   = (size_t)NHC * DC;     // 4194304
    const size_t KN   = (size_t)KHC * DC;     // 2097152
    const size_t FN   = (size_t)FC * DC;      // 16777216
    const size_t QKVN = QN + 2 * KN;          // 8388608
    const size_t oqkv0 = 0, oqkv1 = QKVN;
    const size_t oo0 = 2 * QKVN,      oo1 = oo0 + QN;
    const size_t og0 = oo1 + QN,      og1 = og0 + FN;
    const size_t ou0 = og1 + FN,      ou1 = ou0 + FN;
    const size_t od0 = ou1 + FN,      od1 = od0 + FN;

    // [launch 0] all weight conversions in one kernel
    {
        CvtJobs J;
        const float* srcs[NJOBS] = {q0w, k0w, v0w, q1w, k1w, v1w, o0w, o1w,
                                    gt0, gt1, up0, up1, dw0, dw1};
        const size_t offs[NJOBS] = {oqkv0, oqkv0 + QN, oqkv0 + QN + KN,
                                    oqkv1, oqkv1 + QN, oqkv1 + QN + KN,
                                    oo0, oo1, og0, og1, ou0, ou1, od0, od1};
        const size_t lens[NJOBS] = {QN, KN, KN, QN, KN, KN, QN, QN,
                                    FN, FN, FN, FN, FN, FN};
        int blk = 0;
        for (int j = 0; j < NJOBS; ++j) {
            J.src[j] = srcs[j];
            J.h[j] = wh + offs[j];
            J.l[j] = wl + offs[j];
            J.startblk[j] = blk;
            blk += (int)(lens[j] / 2048);
        }
        J.startblk[NJOBS] = blk;
        cvt_all_kernel<<<blk, 256>>>(J);
    }

    // [launch 1] pre-attn rmsnorm, both streams
    {
        dim3 g(BB * T0C, 2);
        rmsnorm2_kernel<<<g, 256>>>(x0, x1, preh, prel, pa0, pa1, 0);
    }

    // [launches 2-4] pads so the profiler (-s 5 -c 1) lands on the QKV GEMM
    pad_kernel<<<1, 32>>>();
    pad_kernel<<<1, 32>>>();
    pad_kernel<<<1, 32>>>();

    // [launch 5] fused QKV projection (packed Nout=4096)
    {
        dim3 g(4096 / GBN, T0C / GBM, 4);
        gemm_tc<<<g, 256, TC_SMEM_BYTES>>>(preh, prel, wh + oqkv0, wl + oqkv0, wh + oqkv1, wl + oqkv1,
                                           qkv, DC, 4096, 0, 0, 0, 0, 0, 0, 0, 0);
    }

    // [launch 6] RoPE + scale + split to bf16 hi/lo
    rope_split_kernel<<<BB * TOTC, 256>>>(qkv, pos, qhb, qlb, khb, klb, vhb, vlb);

    // [launch 7] attention (mma.sync flash) -> writes ench/encl directly
    {
        dim3 ga(TOTC / ATT_BM, NC, BB);
        attn_mma_kernel<<<ga, 256, ATT_SMEM>>>(qhb, qlb, khb, klb, vhb, vlb, ench, encl);
    }

    // [launch 8] O projection + residual
    {
        dim3 go(DC / GBN, T0C / GBM, 4);
        gemm_tc<<<go, 256, TC_SMEM_BYTES>>>(ench, encl, wh + oo0, wl + oo0, wh + oo1, wl + oo1,
                                            res, NHC, DC, 2, x0, x1, 0, 0, 0, 0, 0);
    }

    // [launch 9] pre-ffw rmsnorm, both streams
    {
        dim3 g(BB * T0C, 2);
        rmsnorm2_kernel<<<g, 256>>>(res, res, hidh, hidl, pf0, pf1, 1);
    }

    // [launches 10-11] gate (gelu) then up (fused gelu(gate)*up split) projections
    {
        dim3 gf(FC / GBN, T0C / GBM, 4);
        gemm_tc<<<gf, 256, TC_SMEM_BYTES>>>(hidh, hidl, wh + og0, wl + og0, wh + og1, wl + og1,
                                            gate, DC, FC, 1, 0, 0, 0, 0, 0, 0, 0);
        gemm_tc<<<gf, 256, TC_SMEM_BYTES>>>(hidh, hidl, wh + ou0, wl + ou0, wh + ou1, wl + ou1,
                                            gate, DC, FC, 3, 0, 0, 0, 0, gate, guh, gul);
    }

    // [launch 12] down projection + residual -> out (stream-major)
    {
        dim3 gd(DC / GBN, T0C / GBM, 4);
        gemm_tc<<<gd, 256, TC_SMEM_BYTES>>>(guh, gul, wh + od0, wl + od0, wh + od1, wl + od1,
                                            out, FC, DC, 2, res, 0, 1, 1, 0, 0, 0);
    }
}